// round 13
// baseline (speedup 1.0000x reference)
#include <cuda_runtime.h>
#include <cuda_fp16.h>
#include <math.h>

#define NPAD 129     // fp32 smem layout (kA), float2 units
#define SPAD 129     // fp16 smem layout (kB/kC), half2 units
#define NT   512
#define PI_F 3.14159265358979f

typedef __half2 c16;  // packed complex: (re, im) in half2

// ---------------- device scratch (static: no allocation allowed) -------------
__device__ float2  g_ihat [64  * 16384];   // FFT2(image), digit-rev layout (fp32)
__device__ __half2 g_u1hat[1024 * 16384];  // FFT2(|u1|),  digit-rev layout (fp16)
__device__ float   g_psi  [16  * 16384];   // Morlet bank, digit-rev (fp32, kB)
__device__ __half  g_psih [16  * 16384];   // Morlet bank, digit-rev (fp16*scale, kC)
__device__ float   g_s0   [64];
__device__ float   g_s1part[1024];
__device__ float   g_s2part[6144];

// digit-reversal for radix [8,4,4] DIF: freq f -> storage position
__device__ __forceinline__ int dperm(int f) {
    return ((f & 7) << 4) | (((f >> 3) & 3) << 2) | (f >> 5);
}

// ---------------- filter bank, stored pre-permuted ---------------------------
__global__ void init_psi_kernel() {
    int idx = blockIdx.x * blockDim.x + threadIdx.x;
    if (idx >= 16 * 16384) return;
    int fc = idx & 127;
    int fr = (idx >> 7) & 127;
    int l  = (idx >> 14) & 3;
    int j  = idx >> 16;
    const float w = 2.f * PI_F / 128.f;
    float fx = (float)((fr < 64) ? fr : fr - 128) * w;
    float fy = (float)((fc < 64) ? fc : fc - 128) * w;
    float k0 = (3.f * PI_F / 4.f) / (float)(1 << j);
    float sg = 0.8f * (float)(1 << j);
    float th = PI_F * (float)l / 4.f;
    float k0x = k0 * cosf(th), k0y = k0 * sinf(th);
    float hs = 0.5f * sg * sg;
    float beta = expf(-hs * k0 * k0);
    float gs = expf(-hs * ((fx - k0x) * (fx - k0x) + (fy - k0y) * (fy - k0y)));
    float g0 = expf(-hs * (fx * fx + fy * fy));
    float v = gs - beta * g0;
    int pos = ((j * 4 + l) << 14) + (dperm(fr) << 7) + dperm(fc);
    g_psi[pos]  = v;
    g_psih[pos] = __float2half(v * (1.f / 16384.f));  // pre-scaled for kC
}

// ---------------- half2 complex primitives -----------------------------------
#define H2(a, b) __floats2half2_rn((a), (b))
__device__ __forceinline__ c16 hswap(c16 v) { return __lowhigh2highlow(v); }
// z * (c + d i) with cc = (c,c), dd = (-d, d)
__device__ __forceinline__ c16 hcmul(c16 z, c16 cc, c16 dd) {
    return __hfma2(hswap(z), dd, __hmul2(z, cc));
}

template <bool INV>
__device__ __forceinline__ void hbfly4(c16* x) {
    c16 t0 = __hadd2(x[0], x[2]), t1 = __hsub2(x[0], x[2]);
    c16 t2 = __hadd2(x[1], x[3]), t3 = __hsub2(x[1], x[3]);
    x[0] = __hadd2(t0, t2); x[2] = __hsub2(t0, t2);
    c16 s = hswap(t3);
    c16 PIh = H2(1.f, -1.f), NIh = H2(-1.f, 1.f);
    if (!INV) { x[1] = __hfma2(s, PIh, t1); x[3] = __hfma2(s, NIh, t1); }
    else      { x[1] = __hfma2(s, NIh, t1); x[3] = __hfma2(s, PIh, t1); }
}

template <bool INV>
__device__ __forceinline__ void hbfly8(c16* x) {
    const float Cf = 0.70710678118654752f;
    c16 e[4] = {x[0], x[2], x[4], x[6]};
    c16 o[4] = {x[1], x[3], x[5], x[7]};
    hbfly4<INV>(e);
    hbfly4<INV>(o);
    c16 CCh = H2(Cf, Cf), mCmCh = H2(-Cf, -Cf);
    if (!INV) {
        c16 CmCh = H2(Cf, -Cf);
        o[1] = hcmul(o[1], CCh, CmCh);                 // * (C, -C)
        o[2] = __hmul2(hswap(o[2]), H2(1.f, -1.f));    // * -i
        o[3] = hcmul(o[3], mCmCh, CmCh);               // * (-C, -C)
    } else {
        c16 mCCh = H2(-Cf, Cf);
        o[1] = hcmul(o[1], CCh, mCCh);                 // * (C, C)
        o[2] = __hmul2(hswap(o[2]), H2(-1.f, 1.f));    // * +i
        o[3] = hcmul(o[3], mCmCh, mCCh);               // * (-C, C)
    }
    x[0] = __hadd2(e[0], o[0]); x[4] = __hsub2(e[0], o[0]);
    x[1] = __hadd2(e[1], o[1]); x[5] = __hsub2(e[1], o[1]);
    x[2] = __hadd2(e[2], o[2]); x[6] = __hsub2(e[2], o[2]);
    x[3] = __hadd2(e[3], o[3]); x[7] = __hsub2(e[3], o[3]);
}

// combined [r4-mid + r4-last] on 16 points, half2.  hd = fwd or inv table.
template <bool INV>
__device__ __forceinline__ void hcomb_regs(c16* x, const c16* hc, const c16* hd) {
    if (!INV) {
#pragma unroll
        for (int j = 0; j < 4; j++) {
            c16 y[4];
#pragma unroll
            for (int k = 0; k < 4; k++) y[k] = x[j + 4 * k];
            hbfly4<false>(y);
#pragma unroll
            for (int k = 1; k < 4; k++) {
                int ti = 8 * j * k;
                y[k] = hcmul(y[k], hc[ti], hd[ti]);
            }
#pragma unroll
            for (int k = 0; k < 4; k++) x[j + 4 * k] = y[k];
        }
#pragma unroll
        for (int a = 0; a < 4; a++) hbfly4<false>(&x[4 * a]);
    } else {
#pragma unroll
        for (int a = 0; a < 4; a++) hbfly4<true>(&x[4 * a]);
#pragma unroll
        for (int j = 0; j < 4; j++) {
            c16 y[4];
#pragma unroll
            for (int k = 0; k < 4; k++) y[k] = x[j + 4 * k];
#pragma unroll
            for (int k = 1; k < 4; k++) {
                int ti = 8 * j * k;
                y[k] = hcmul(y[k], hc[ti], hd[ti]);
            }
            hbfly4<true>(y);
#pragma unroll
            for (int k = 0; k < 4; k++) x[j + 4 * k] = y[k];
        }
    }
}

// ---------------- fp32 butterflies (kA only) ---------------------------------
template <bool INV>
__device__ __forceinline__ void bfly4(float2* x) {
    float t0r = x[0].x + x[2].x, t0i = x[0].y + x[2].y;
    float t1r = x[0].x - x[2].x, t1i = x[0].y - x[2].y;
    float t2r = x[1].x + x[3].x, t2i = x[1].y + x[3].y;
    float t3r = x[1].x - x[3].x, t3i = x[1].y - x[3].y;
    x[0].x = t0r + t2r; x[0].y = t0i + t2i;
    x[2].x = t0r - t2r; x[2].y = t0i - t2i;
    if (!INV) {
        x[1].x = t1r + t3i; x[1].y = t1i - t3r;
        x[3].x = t1r - t3i; x[3].y = t1i + t3r;
    } else {
        x[1].x = t1r - t3i; x[1].y = t1i + t3r;
        x[3].x = t1r + t3i; x[3].y = t1i - t3r;
    }
}

template <bool INV>
__device__ __forceinline__ void bfly8(float2* x) {
    const float C = 0.70710678118654752f;
    float t0r = x[0].x + x[4].x, t0i = x[0].y + x[4].y;
    float t1r = x[0].x - x[4].x, t1i = x[0].y - x[4].y;
    float t2r = x[2].x + x[6].x, t2i = x[2].y + x[6].y;
    float t3r = x[2].x - x[6].x, t3i = x[2].y - x[6].y;
    float e0r = t0r + t2r, e0i = t0i + t2i;
    float e2r = t0r - t2r, e2i = t0i - t2i;
    float e1r, e1i, e3r, e3i;
    if (!INV) { e1r = t1r + t3i; e1i = t1i - t3r; e3r = t1r - t3i; e3i = t1i + t3r; }
    else      { e1r = t1r - t3i; e1i = t1i + t3r; e3r = t1r + t3i; e3i = t1i - t3r; }
    float u0r = x[1].x + x[5].x, u0i = x[1].y + x[5].y;
    float u1r = x[1].x - x[5].x, u1i = x[1].y - x[5].y;
    float u2r = x[3].x + x[7].x, u2i = x[3].y + x[7].y;
    float u3r = x[3].x - x[7].x, u3i = x[3].y - x[7].y;
    float o0r = u0r + u2r, o0i = u0i + u2i;
    float o2r = u0r - u2r, o2i = u0i - u2i;
    float o1r, o1i, o3r, o3i;
    if (!INV) { o1r = u1r + u3i; o1i = u1i - u3r; o3r = u1r - u3i; o3i = u1i + u3r; }
    else      { o1r = u1r - u3i; o1i = u1i + u3r; o3r = u1r + u3i; o3i = u1i - u3r; }
    float w1r, w1i, w2r, w2i, w3r, w3i;
    if (!INV) {
        w1r = C * (o1r + o1i); w1i = C * (o1i - o1r);
        w2r = o2i;             w2i = -o2r;
        w3r = C * (o3i - o3r); w3i = -C * (o3r + o3i);
    } else {
        w1r = C * (o1r - o1i); w1i = C * (o1i + o1r);
        w2r = -o2i;            w2i = o2r;
        w3r = -C * (o3r + o3i); w3i = C * (o3r - o3i);
    }
    x[0].x = e0r + o0r; x[0].y = e0i + o0i;
    x[1].x = e1r + w1r; x[1].y = e1i + w1i;
    x[2].x = e2r + w2r; x[2].y = e2i + w2i;
    x[3].x = e3r + w3r; x[3].y = e3i + w3i;
    x[4].x = e0r - o0r; x[4].y = e0i - o0i;
    x[5].x = e1r - w1r; x[5].y = e1i - w1i;
    x[6].x = e2r - w2r; x[6].y = e2i - w2i;
    x[7].x = e3r - w3r; x[7].y = e3i - w3i;
}

template <bool INV>
__device__ __forceinline__ void comb_regs(float2* x, const float* twr, const float* twi) {
    if (!INV) {
#pragma unroll
        for (int j = 0; j < 4; j++) {
            float2 y[4];
#pragma unroll
            for (int k = 0; k < 4; k++) y[k] = x[j + 4 * k];
            bfly4<false>(y);
#pragma unroll
            for (int k = 1; k < 4; k++) {
                int ti = 8 * j * k;
                float wr = twr[ti], wi = twi[ti];
                float a = y[k].x, b = y[k].y;
                y[k].x = a * wr - b * wi; y[k].y = a * wi + b * wr;
            }
#pragma unroll
            for (int k = 0; k < 4; k++) x[j + 4 * k] = y[k];
        }
#pragma unroll
        for (int a = 0; a < 4; a++) bfly4<false>(&x[4 * a]);
    } else {
#pragma unroll
        for (int a = 0; a < 4; a++) bfly4<true>(&x[4 * a]);
#pragma unroll
        for (int j = 0; j < 4; j++) {
            float2 y[4];
#pragma unroll
            for (int k = 0; k < 4; k++) y[k] = x[j + 4 * k];
#pragma unroll
            for (int k = 1; k < 4; k++) {
                int ti = 8 * j * k;
                float wr = twr[ti], wi = -twi[ti];
                float a = y[k].x, b = y[k].y;
                y[k].x = a * wr - b * wi; y[k].y = a * wi + b * wr;
            }
            bfly4<true>(y);
#pragma unroll
            for (int k = 0; k < 4; k++) x[j + 4 * k] = y[k];
        }
    }
}

// ---------------- fp32 smem passes (kA only) ---------------------------------
template <int BS, bool INV, int DIM>
__device__ __forceinline__ void comb_stage(float2* sc, const float* twr, const float* twi) {
    for (int idx = threadIdx.x; idx < 1024; idx += BS) {
        int q = idx & 127, g = idx >> 7;
        int base = (DIM == 0) ? q * NPAD + (g << 4) : (g << 4) * NPAD + q;
        int step = (DIM == 0) ? 1 : NPAD;
        float2 x[16];
#pragma unroll
        for (int m = 0; m < 16; m++) x[m] = sc[base + m * step];
        comb_regs<INV>(x, twr, twi);
#pragma unroll
        for (int m = 0; m < 16; m++) sc[base + m * step] = x[m];
    }
    __syncthreads();
}

template <int BS, bool INV, int DIM>
__device__ __forceinline__ void r8_stage(float2* sc, const float* twr, const float* twi) {
    for (int idx = threadIdx.x; idx < 2048; idx += BS) {
        int q = idx & 127, j = idx >> 7;
        int base = (DIM == 0) ? q * NPAD + j : j * NPAD + q;
        int step = (DIM == 0) ? 16 : 16 * NPAD;
        float2 x[8];
#pragma unroll
        for (int k = 0; k < 8; k++) x[k] = sc[base + k * step];
        if (INV) {
#pragma unroll
            for (int k = 1; k < 8; k++) {
                int t = j * k;
                float wr = twr[t], wi = -twi[t];
                float a = x[k].x, b = x[k].y;
                x[k].x = a * wr - b * wi; x[k].y = a * wi + b * wr;
            }
        }
        bfly8<INV>(x);
        if (!INV) {
#pragma unroll
            for (int k = 1; k < 8; k++) {
                int t = j * k;
                float wr = twr[t], wi = twi[t];
                float a = x[k].x, b = x[k].y;
                x[k].x = a * wr - b * wi; x[k].y = a * wi + b * wr;
            }
        }
#pragma unroll
        for (int k = 0; k < 8; k++) sc[base + k * step] = x[k];
    }
    __syncthreads();
}

// ---------------- half2-native smem passes (kB / kC) -------------------------
template <int BS, bool INV, int DIM>
__device__ __forceinline__ void hcomb_stage(c16* sh, const c16* hc, const c16* hd) {
    for (int idx = threadIdx.x; idx < 1024; idx += BS) {
        int q = idx & 127, g = idx >> 7;
        int base = (DIM == 0) ? q * SPAD + (g << 4) : (g << 4) * SPAD + q;
        int step = (DIM == 0) ? 1 : SPAD;
        c16 x[16];
#pragma unroll
        for (int m = 0; m < 16; m++) x[m] = sh[base + m * step];
        hcomb_regs<INV>(x, hc, hd);
#pragma unroll
        for (int m = 0; m < 16; m++) sh[base + m * step] = x[m];
    }
    __syncthreads();
}

template <int BS, bool INV, int DIM>
__device__ __forceinline__ void hr8_stage(c16* sh, const c16* hc, const c16* hd) {
    for (int idx = threadIdx.x; idx < 2048; idx += BS) {
        int q = idx & 127, j = idx >> 7;
        int base = (DIM == 0) ? q * SPAD + j : j * SPAD + q;
        int step = (DIM == 0) ? 16 : 16 * SPAD;
        c16 x[8];
#pragma unroll
        for (int k = 0; k < 8; k++) x[k] = sh[base + k * step];
        if (INV) {
#pragma unroll
            for (int k = 1; k < 8; k++) { int t = j * k; x[k] = hcmul(x[k], hc[t], hd[t]); }
        }
        hbfly8<INV>(x);
        if (!INV) {
#pragma unroll
            for (int k = 1; k < 8; k++) { int t = j * k; x[k] = hcmul(x[k], hc[t], hd[t]); }
        }
#pragma unroll
        for (int k = 0; k < 8; k++) sh[base + k * step] = x[k];
    }
    __syncthreads();
}

// kB entry: (fp32 gmem src * fp32 psi * scale) -> half2 comb inv dim0 -> smem
template <int BS>
__device__ __forceinline__ void hpass_load_inv0_f32(c16* sh, const float2* __restrict__ src,
                                                    const float* __restrict__ psi,
                                                    const c16* hc, const c16* hdi) {
    const float scale = 1.f / 16384.f;
    for (int idx = threadIdx.x; idx < 1024; idx += BS) {
        int rr = idx & 127, g = idx >> 7;
        int gbase = rr * 128 + (g << 4);
        const float4* s4 = reinterpret_cast<const float4*>(src + gbase);
        const float4* p4 = reinterpret_cast<const float4*>(psi + gbase);
        c16 x[16];
#pragma unroll
        for (int m8 = 0; m8 < 4; m8++) {
            float4 p = p4[m8];
            float4 v0 = s4[m8 * 2], v1 = s4[m8 * 2 + 1];
            float pa = p.x * scale, pb = p.y * scale, pc = p.z * scale, pd = p.w * scale;
            x[m8 * 4 + 0] = H2(v0.x * pa, v0.y * pa);
            x[m8 * 4 + 1] = H2(v0.z * pb, v0.w * pb);
            x[m8 * 4 + 2] = H2(v1.x * pc, v1.y * pc);
            x[m8 * 4 + 3] = H2(v1.z * pd, v1.w * pd);
        }
        hcomb_regs<true>(x, hc, hdi);
        int base = rr * SPAD + (g << 4);
#pragma unroll
        for (int m = 0; m < 16; m++) sh[base + m] = x[m];
    }
    __syncthreads();
}

// final inverse r8 dim1 + |.|; optionally write mag back as half2(mag,0)
template <int BS, bool WRITE>
__device__ __forceinline__ float hpass_inv1_r8_mag(c16* sh, const c16* hc, const c16* hdi) {
    float local = 0.f;
    for (int idx = threadIdx.x; idx < 2048; idx += BS) {
        int q = idx & 127, j = idx >> 7;
        int base = j * SPAD + q;
        int step = 16 * SPAD;
        c16 x[8];
#pragma unroll
        for (int k = 0; k < 8; k++) x[k] = sh[base + k * step];
#pragma unroll
        for (int k = 1; k < 8; k++) { int t = j * k; x[k] = hcmul(x[k], hc[t], hdi[t]); }
        hbfly8<true>(x);
#pragma unroll
        for (int k = 0; k < 8; k++) {
            float2 v = __half22float2(x[k]);
            float mag = sqrtf(v.x * v.x + v.y * v.y);
            local += mag;
            if (WRITE) sh[base + k * step] = __floats2half2_rn(mag, 0.f);
        }
    }
    __syncthreads();
    return local;
}

// final forward comb dim1 -> gmem half2 store (coalesced per leg)
template <int BS>
__device__ __forceinline__ void hpass_fwd1_store(c16* sh, __half2* __restrict__ dst,
                                                 const c16* hc, const c16* hdf) {
    for (int idx = threadIdx.x; idx < 1024; idx += BS) {
        int q = idx & 127, g = idx >> 7;
        int base = (g << 4) * SPAD + q;
        c16 x[16];
#pragma unroll
        for (int m = 0; m < 16; m++) x[m] = sh[base + m * SPAD];
        hcomb_regs<false>(x, hc, hdf);
#pragma unroll
        for (int m = 0; m < 16; m++) dst[((g << 4) + m) * 128 + q] = x[m];
    }
}

#define INIT_TWIDDLES_F32()                                                    \
    do {                                                                       \
        if (threadIdx.x < 128) {                                               \
            float sv, cv;                                                      \
            __sincosf(-2.f * PI_F * (float)threadIdx.x / 128.f, &sv, &cv);     \
            s_twr[threadIdx.x] = cv;                                           \
            s_twi[threadIdx.x] = sv;                                           \
        }                                                                      \
    } while (0)

// half2 twiddle tables: hc=(c,c), hdf=(-d,d) fwd, hdi=(d,-d) inv, w=(c,d)=e^{-i2pi t/128}
#define INIT_TWIDDLES_H2()                                                     \
    do {                                                                       \
        if (threadIdx.x < 128) {                                               \
            float sv, cv;                                                      \
            __sincosf(-2.f * PI_F * (float)threadIdx.x / 128.f, &sv, &cv);     \
            s_hc [threadIdx.x] = __floats2half2_rn(cv, cv);                    \
            s_hdf[threadIdx.x] = __floats2half2_rn(-sv, sv);                   \
            s_hdi[threadIdx.x] = __floats2half2_rn(sv, -sv);                   \
        }                                                                      \
    } while (0)

// warp-shuffle block reduction (deterministic); result valid in tid 0
template <int BS>
__device__ __forceinline__ float block_sum(float v, float* red) {
#pragma unroll
    for (int o = 16; o; o >>= 1) v += __shfl_xor_sync(0xffffffffu, v, o);
    if ((threadIdx.x & 31) == 0) red[threadIdx.x >> 5] = v;
    __syncthreads();
    float s = 0.f;
    if (threadIdx.x < 32) {
        s = (threadIdx.x < BS / 32) ? red[threadIdx.x] : 0.f;
#pragma unroll
        for (int o = 16; o; o >>= 1) s += __shfl_xor_sync(0xffffffffu, s, o);
    }
    return s;
}

// ---------------- stage A: i_hat = FFT2(image), s0 (fp32) --------------------
__global__ __launch_bounds__(NT, 1) void kA(const float* __restrict__ img) {
    extern __shared__ float2 sc[];
    __shared__ float s_twr[128], s_twi[128];
    __shared__ float red[32];
    int b = blockIdx.x;
    int tid = threadIdx.x;
    INIT_TWIDDLES_F32();

    float local = 0.f;
    for (int idx = tid; idx < 16384; idx += NT) {
        float v = img[b * 16384 + idx];
        int r = idx >> 7, c = idx & 127;
        sc[r * NPAD + c] = make_float2(v, 0.f);
        local += v;
    }
    float s = block_sum<NT>(local, red);
    if (tid == 0) g_s0[b] = s * (1.f / 16384.f);
    __syncthreads();

    r8_stage<NT, false, 0>(sc, s_twr, s_twi);
    comb_stage<NT, false, 0>(sc, s_twr, s_twi);
    r8_stage<NT, false, 1>(sc, s_twr, s_twi);
    comb_stage<NT, false, 1>(sc, s_twr, s_twi);

    for (int idx = tid; idx < 16384; idx += NT) {
        int r = idx >> 7, c = idx & 127;
        g_ihat[b * 16384 + idx] = sc[r * NPAD + c];
    }
}

// ---------------- stage B: u1 = |ifft2(i_hat*psi)|, s1 partial, u1_hat -------
__global__ __launch_bounds__(NT, 2) void kB() {
    extern __shared__ c16 shb[];
    __shared__ c16 s_hc[128], s_hdf[128], s_hdi[128];
    __shared__ float red[32];
    int bi = blockIdx.x;              // b*16 + j1*4 + l1
    int b  = bi >> 4;
    int j1 = (bi >> 2) & 3;
    int tid = threadIdx.x;
    INIT_TWIDDLES_H2();
    __syncthreads();

    const float2* src = g_ihat + (size_t)b * 16384;
    const float*  psi1 = g_psi + (((size_t)(bi & 15)) << 14);

    hpass_load_inv0_f32<NT>(shb, src, psi1, s_hc, s_hdi);    // inv dim0: comb16
    hr8_stage<NT, true, 0>(shb, s_hc, s_hdi);                // inv dim0: r8
    hcomb_stage<NT, true, 1>(shb, s_hc, s_hdi);              // inv dim1: comb16
    float local = hpass_inv1_r8_mag<NT, true>(shb, s_hc, s_hdi); // inv dim1: r8+mag
    float s = block_sum<NT>(local, red);
    if (tid == 0) g_s1part[bi] = s;
    __syncthreads();

    if (j1 < 3) {                     // j1 == 3 never consumed by second order
        hr8_stage<NT, false, 0>(shb, s_hc, s_hdf);
        hcomb_stage<NT, false, 0>(shb, s_hc, s_hdf);
        hr8_stage<NT, false, 1>(shb, s_hc, s_hdf);
        hpass_fwd1_store<NT>(shb, g_u1hat + (size_t)bi * 16384, s_hc, s_hdf);
    }
}

// ---------------- stage C: half2-native 4-pass inverse + |.| -----------------
__global__ __launch_bounds__(NT, 2) void kC() {
    extern __shared__ c16 sh[];
    __shared__ c16 s_hc[128], s_hdf[128], s_hdi[128];
    __shared__ float red[32];
    int bi = blockIdx.x;              // b*96 + pair*16 + l1*4 + l2
    int b    = bi / 96;
    int r96  = bi % 96;
    int pair = r96 >> 4;
    int l1   = (r96 >> 2) & 3;
    int l2   = r96 & 3;
    const int J1[6] = {0, 0, 0, 1, 1, 2};
    const int J2[6] = {1, 2, 3, 2, 3, 3};
    int j1 = J1[pair], j2 = J2[pair];
    int tid = threadIdx.x;
    INIT_TWIDDLES_H2();
    __syncthreads();

    const __half2* src = g_u1hat + (((size_t)b * 16 + j1 * 4 + l1) << 14);
    const __half*  psi = g_psih + (((size_t)j2 * 4 + l2) << 14);

    // ---- C1: gmem(half) load * psih(pre-scaled) -> comb16 inv dim0 -> smem --
#pragma unroll
    for (int it = 0; it < 2; it++) {
        int idx = tid + it * NT;
        int rr = idx & 127, g = idx >> 7;
        const uint4* s4 = reinterpret_cast<const uint4*>(src + rr * 128 + (g << 4));
        const uint4* p4 = reinterpret_cast<const uint4*>(psi + rr * 128 + (g << 4));
        uint4 svv[4] = {s4[0], s4[1], s4[2], s4[3]};
        uint4 pvv[2] = {p4[0], p4[1]};
        const c16*    sh2 = reinterpret_cast<const c16*>(svv);
        const __half* ph  = reinterpret_cast<const __half*>(pvv);
        c16 x[16];
#pragma unroll
        for (int m = 0; m < 16; m++)
            x[m] = __hmul2(sh2[m], __half2half2(ph[m]));
        hcomb_regs<true>(x, s_hc, s_hdi);
        int base = rr * SPAD + (g << 4);
#pragma unroll
        for (int m = 0; m < 16; m++) sh[base + m] = x[m];
    }
    __syncthreads();

    hr8_stage<NT, true, 0>(sh, s_hc, s_hdi);                  // inv dim0: r8
    hcomb_stage<NT, true, 1>(sh, s_hc, s_hdi);                // inv dim1: comb16
    float local = hpass_inv1_r8_mag<NT, false>(sh, s_hc, s_hdi); // inv dim1: r8+|.|
    float s = block_sum<NT>(local, red);
    if (tid == 0) g_s2part[bi] = s;
}

// ---------------- stage D: deterministic reduce + MLP ------------------------
__global__ void kD(const float* __restrict__ fc1w, const float* __restrict__ fc1b,
                   const float* __restrict__ fc2w, const float* __restrict__ fc2b,
                   float* __restrict__ out) {
    int b = threadIdx.x;
    if (b >= 64) return;
    float s[11];
    s[0] = g_s0[b];
    for (int j = 0; j < 4; j++) {
        float acc = 0.f;
        for (int l = 0; l < 4; l++) acc += g_s1part[b * 16 + j * 4 + l];
        s[1 + j] = acc * (1.f / (4.f * 16384.f));
    }
    for (int p = 0; p < 6; p++) {
        float acc = 0.f;
        for (int kk = 0; kk < 16; kk++) acc += g_s2part[b * 96 + p * 16 + kk];
        s[5 + p] = acc * (1.f / (16.f * 16384.f));
    }
    float h[4];
    for (int i = 0; i < 4; i++) {
        float a = fc1b[i];
        for (int t = 0; t < 11; t++) a += fc1w[i * 11 + t] * s[t];
        h[i] = fmaxf(a, 0.f);
    }
    for (int kk = 0; kk < 10; kk++) {
        float a = fc2b[kk];
        for (int i = 0; i < 4; i++) a += fc2w[kk * 4 + i] * h[i];
        out[b * 10 + kk] = 1.f / (1.f + expf(-a));
    }
}

// ---------------- launch -----------------------------------------------------
extern "C" void kernel_launch(void* const* d_in, const int* in_sizes, int n_in,
                              void* d_out, int out_size) {
    const float* img  = (const float*)d_in[0];
    const float* fc1w = (const float*)d_in[1];
    const float* fc1b = (const float*)d_in[2];
    const float* fc2w = (const float*)d_in[3];
    const float* fc2b = (const float*)d_in[4];
    float* out = (float*)d_out;

    const size_t smemA  = 128 * NPAD * sizeof(float2);   // 132096 B
    const size_t smemBC = 128 * SPAD * sizeof(__half2);  // 66048 B (2 CTAs/SM)
    cudaFuncSetAttribute(kA, cudaFuncAttributeMaxDynamicSharedMemorySize, (int)smemA);
    cudaFuncSetAttribute(kB, cudaFuncAttributeMaxDynamicSharedMemorySize, (int)smemBC);
    cudaFuncSetAttribute(kC, cudaFuncAttributeMaxDynamicSharedMemorySize, (int)smemBC);

    init_psi_kernel<<<256, 1024>>>();
    kA<<<64, NT, smemA>>>(img);
    kB<<<1024, NT, smemBC>>>();
    kC<<<6144, NT, smemBC>>>();
    kD<<<1, 64>>>(fc1w, fc1b, fc2w, fc2b, out);
}

// round 14
// speedup vs baseline: 1.4157x; 1.4157x over previous
#include <cuda_runtime.h>
#include <cuda_fp16.h>
#include <math.h>

#define NPAD 129     // fp32 smem layout (kA), float2 units
#define SPAD 129     // fp16 smem layout (kB/kC), half2 units
#define NT   512
#define PI_F 3.14159265358979f

typedef unsigned long long u64;

// ---------------- device scratch (static: no allocation allowed) -------------
__device__ float2  g_ihat [64  * 16384];   // FFT2(image), digit-rev layout (fp32)
__device__ __half2 g_u1hat[1024 * 16384];  // FFT2(|u1|),  digit-rev layout (fp16)
__device__ float   g_psi  [16  * 16384];   // Morlet bank, digit-rev (fp32, kB)
__device__ __half  g_psih [16  * 16384];   // Morlet bank, digit-rev (fp16*scale, kC)
__device__ float   g_s0   [64];
__device__ float   g_s1part[1024];
__device__ float   g_s2part[6144];

// digit-reversal for radix [8,4,4] DIF: freq f -> storage position
__device__ __forceinline__ int dperm(int f) {
    return ((f & 7) << 4) | (((f >> 3) & 3) << 2) | (f >> 5);
}

// ---------------- filter bank, stored pre-permuted ---------------------------
__global__ void init_psi_kernel() {
    int idx = blockIdx.x * blockDim.x + threadIdx.x;
    if (idx >= 16 * 16384) return;
    int fc = idx & 127;
    int fr = (idx >> 7) & 127;
    int l  = (idx >> 14) & 3;
    int j  = idx >> 16;
    const float w = 2.f * PI_F / 128.f;
    float fx = (float)((fr < 64) ? fr : fr - 128) * w;
    float fy = (float)((fc < 64) ? fc : fc - 128) * w;
    float k0 = (3.f * PI_F / 4.f) / (float)(1 << j);
    float sg = 0.8f * (float)(1 << j);
    float th = PI_F * (float)l / 4.f;
    float k0x = k0 * cosf(th), k0y = k0 * sinf(th);
    float hs = 0.5f * sg * sg;
    float beta = expf(-hs * k0 * k0);
    float gs = expf(-hs * ((fx - k0x) * (fx - k0x) + (fy - k0y) * (fy - k0y)));
    float g0 = expf(-hs * (fx * fx + fy * fy));
    float v = gs - beta * g0;
    int pos = ((j * 4 + l) << 14) + (dperm(fr) << 7) + dperm(fc);
    g_psi[pos]  = v;
    g_psih[pos] = __float2half(v * (1.f / 16384.f));  // pre-scaled for kC
}

// ---------------- packed f32x2 complex primitives ----------------------------
__device__ __forceinline__ u64 pk2(float r, float i) {
    u64 o; asm("mov.b64 %0, {%1, %2};" : "=l"(o) : "f"(r), "f"(i)); return o;
}
__device__ __forceinline__ void unpk2(u64 v, float& r, float& i) {
    asm("mov.b64 {%0, %1}, %2;" : "=f"(r), "=f"(i) : "l"(v));
}
__device__ __forceinline__ u64 padd(u64 a, u64 b) {
    u64 o; asm("add.rn.f32x2 %0, %1, %2;" : "=l"(o) : "l"(a), "l"(b)); return o;
}
__device__ __forceinline__ u64 psub(u64 a, u64 b) {
    u64 o; asm("sub.rn.f32x2 %0, %1, %2;" : "=l"(o) : "l"(a), "l"(b)); return o;
}
__device__ __forceinline__ u64 pmul(u64 a, u64 b) {
    u64 o; asm("mul.rn.f32x2 %0, %1, %2;" : "=l"(o) : "l"(a), "l"(b)); return o;
}
__device__ __forceinline__ u64 pfma(u64 a, u64 b, u64 c) {
    u64 o; asm("fma.rn.f32x2 %0, %1, %2, %3;" : "=l"(o) : "l"(a), "l"(b), "l"(c)); return o;
}
__device__ __forceinline__ u64 pswap(u64 v) {
    u64 o; asm("{ .reg .b32 l, h; mov.b64 {l, h}, %1; mov.b64 %0, {h, l}; }"
               : "=l"(o) : "l"(v)); return o;
}
// z * (c + d i) with wc = (c,c), wd = (-d, d)
__device__ __forceinline__ u64 pcmul(u64 z, u64 wc, u64 wd) {
    return pfma(pswap(z), wd, pmul(z, wc));
}
// smem half2 <-> packed f32x2
__device__ __forceinline__ u64 ld_cvt(const __half2* p) {
    float2 f = __half22float2(*p); return pk2(f.x, f.y);
}
__device__ __forceinline__ __half2 cvt_st(u64 v) {
    float r, i; unpk2(v, r, i); return __floats2half2_rn(r, i);
}

template <bool INV>
__device__ __forceinline__ void bfly4p(u64* x) {
    const u64 P1M1 = pk2(1.f, -1.f), M1P1 = pk2(-1.f, 1.f);
    u64 t0 = padd(x[0], x[2]), t1 = psub(x[0], x[2]);
    u64 t2 = padd(x[1], x[3]), t3 = psub(x[1], x[3]);
    x[0] = padd(t0, t2); x[2] = psub(t0, t2);
    u64 s = pswap(t3);
    if (!INV) { x[1] = pfma(s, P1M1, t1); x[3] = pfma(s, M1P1, t1); }
    else      { x[1] = pfma(s, M1P1, t1); x[3] = pfma(s, P1M1, t1); }
}

template <bool INV>
__device__ __forceinline__ void bfly8p(u64* x) {
    const float Cf = 0.70710678118654752f;
    u64 e[4] = {x[0], x[2], x[4], x[6]};
    u64 o[4] = {x[1], x[3], x[5], x[7]};
    bfly4p<INV>(e);
    bfly4p<INV>(o);
    const u64 CC = pk2(Cf, Cf), mCmC = pk2(-Cf, -Cf);
    if (!INV) {
        const u64 CmC = pk2(Cf, -Cf);
        o[1] = pfma(pswap(o[1]), CmC, pmul(o[1], CC));    // * (C - Ci)
        o[2] = pmul(pswap(o[2]), pk2(1.f, -1.f));         // * -i
        o[3] = pfma(pswap(o[3]), CmC, pmul(o[3], mCmC));  // * (-C - Ci)
    } else {
        const u64 mCC = pk2(-Cf, Cf);
        o[1] = pfma(pswap(o[1]), mCC, pmul(o[1], CC));    // * (C + Ci)
        o[2] = pmul(pswap(o[2]), pk2(-1.f, 1.f));         // * +i
        o[3] = pfma(pswap(o[3]), mCC, pmul(o[3], mCmC));  // * (-C + Ci)
    }
    x[0] = padd(e[0], o[0]); x[4] = psub(e[0], o[0]);
    x[1] = padd(e[1], o[1]); x[5] = psub(e[1], o[1]);
    x[2] = padd(e[2], o[2]); x[6] = psub(e[2], o[2]);
    x[3] = padd(e[3], o[3]); x[7] = psub(e[3], o[3]);
}

// combined [r4-mid (stride4) + r4-last (stride1)] on 16 packed points
template <bool INV>
__device__ __forceinline__ void comb_regsp(u64* x, const u64* wc, const u64* wd) {
    if (!INV) {
#pragma unroll
        for (int j = 0; j < 4; j++) {
            u64 y[4];
#pragma unroll
            for (int k = 0; k < 4; k++) y[k] = x[j + 4 * k];
            bfly4p<false>(y);
#pragma unroll
            for (int k = 1; k < 4; k++) {
                int ti = 8 * j * k;
                y[k] = pcmul(y[k], wc[ti], wd[ti]);
            }
#pragma unroll
            for (int k = 0; k < 4; k++) x[j + 4 * k] = y[k];
        }
#pragma unroll
        for (int a = 0; a < 4; a++) bfly4p<false>(&x[4 * a]);
    } else {
#pragma unroll
        for (int a = 0; a < 4; a++) bfly4p<true>(&x[4 * a]);
#pragma unroll
        for (int j = 0; j < 4; j++) {
            u64 y[4];
#pragma unroll
            for (int k = 0; k < 4; k++) y[k] = x[j + 4 * k];
#pragma unroll
            for (int k = 1; k < 4; k++) {
                int ti = 8 * j * k;
                y[k] = pcmul(y[k], wc[ti], wd[ti]);
            }
            bfly4p<true>(y);
#pragma unroll
            for (int k = 0; k < 4; k++) x[j + 4 * k] = y[k];
        }
    }
}

// ---------------- packed smem passes (half2 storage, f32x2 compute) ----------
template <int BS, bool INV, int DIM>
__device__ __forceinline__ void hcomb_stage(__half2* sh, const u64* wc, const u64* wd) {
    for (int idx = threadIdx.x; idx < 1024; idx += BS) {
        int q = idx & 127, g = idx >> 7;
        int base = (DIM == 0) ? q * SPAD + (g << 4) : (g << 4) * SPAD + q;
        int step = (DIM == 0) ? 1 : SPAD;
        u64 x[16];
#pragma unroll
        for (int m = 0; m < 16; m++) x[m] = ld_cvt(&sh[base + m * step]);
        comb_regsp<INV>(x, wc, wd);
#pragma unroll
        for (int m = 0; m < 16; m++) sh[base + m * step] = cvt_st(x[m]);
    }
    __syncthreads();
}

template <int BS, bool INV, int DIM>
__device__ __forceinline__ void hr8_stage(__half2* sh, const u64* wc, const u64* wd) {
    for (int idx = threadIdx.x; idx < 2048; idx += BS) {
        int q = idx & 127, j = idx >> 7;
        int base = (DIM == 0) ? q * SPAD + j : j * SPAD + q;
        int step = (DIM == 0) ? 16 : 16 * SPAD;
        u64 x[8];
#pragma unroll
        for (int k = 0; k < 8; k++) x[k] = ld_cvt(&sh[base + k * step]);
        if (INV) {
#pragma unroll
            for (int k = 1; k < 8; k++) { int t = j * k; x[k] = pcmul(x[k], wc[t], wd[t]); }
        }
        bfly8p<INV>(x);
        if (!INV) {
#pragma unroll
            for (int k = 1; k < 8; k++) { int t = j * k; x[k] = pcmul(x[k], wc[t], wd[t]); }
        }
#pragma unroll
        for (int k = 0; k < 8; k++) sh[base + k * step] = cvt_st(x[k]);
    }
    __syncthreads();
}

// kB entry: (fp32 gmem src * fp32 psi * scale) -> packed comb inv dim0 -> smem
template <int BS>
__device__ __forceinline__ void hpass_load_inv0_f32(__half2* sh, const float2* __restrict__ src,
                                                    const float* __restrict__ psi,
                                                    const u64* wc, const u64* wdi) {
    const float scale = 1.f / 16384.f;
    for (int idx = threadIdx.x; idx < 1024; idx += BS) {
        int rr = idx & 127, g = idx >> 7;
        int gbase = rr * 128 + (g << 4);
        const float4* s4 = reinterpret_cast<const float4*>(src + gbase);
        const float4* p4 = reinterpret_cast<const float4*>(psi + gbase);
        u64 x[16];
#pragma unroll
        for (int m8 = 0; m8 < 4; m8++) {
            float4 p = p4[m8];
            float4 v0 = s4[m8 * 2], v1 = s4[m8 * 2 + 1];
            float pa = p.x * scale, pb = p.y * scale, pc = p.z * scale, pd = p.w * scale;
            x[m8 * 4 + 0] = pk2(v0.x * pa, v0.y * pa);
            x[m8 * 4 + 1] = pk2(v0.z * pb, v0.w * pb);
            x[m8 * 4 + 2] = pk2(v1.x * pc, v1.y * pc);
            x[m8 * 4 + 3] = pk2(v1.z * pd, v1.w * pd);
        }
        comb_regsp<true>(x, wc, wdi);
        int base = rr * SPAD + (g << 4);
#pragma unroll
        for (int m = 0; m < 16; m++) sh[base + m] = cvt_st(x[m]);
    }
    __syncthreads();
}

// final inverse r8 dim1 + |.|; optionally write mag back as half2(mag,0)
template <int BS, bool WRITE>
__device__ __forceinline__ float hpass_inv1_r8_mag(__half2* sh, const u64* wc, const u64* wdi) {
    float local = 0.f;
    for (int idx = threadIdx.x; idx < 2048; idx += BS) {
        int q = idx & 127, j = idx >> 7;
        int base = j * SPAD + q;
        int step = 16 * SPAD;
        u64 x[8];
#pragma unroll
        for (int k = 0; k < 8; k++) x[k] = ld_cvt(&sh[base + k * step]);
#pragma unroll
        for (int k = 1; k < 8; k++) { int t = j * k; x[k] = pcmul(x[k], wc[t], wdi[t]); }
        bfly8p<true>(x);
#pragma unroll
        for (int k = 0; k < 8; k++) {
            float xr, xi; unpk2(x[k], xr, xi);
            float mag = sqrtf(xr * xr + xi * xi);
            local += mag;
            if (WRITE) sh[base + k * step] = __floats2half2_rn(mag, 0.f);
        }
    }
    __syncthreads();
    return local;
}

// final forward comb dim1 -> gmem half2 store (coalesced per leg)
template <int BS>
__device__ __forceinline__ void hpass_fwd1_store(__half2* sh, __half2* __restrict__ dst,
                                                 const u64* wc, const u64* wdf) {
    for (int idx = threadIdx.x; idx < 1024; idx += BS) {
        int q = idx & 127, g = idx >> 7;
        int base = (g << 4) * SPAD + q;
        u64 x[16];
#pragma unroll
        for (int m = 0; m < 16; m++) x[m] = ld_cvt(&sh[base + m * SPAD]);
        comb_regsp<false>(x, wc, wdf);
#pragma unroll
        for (int m = 0; m < 16; m++) dst[((g << 4) + m) * 128 + q] = cvt_st(x[m]);
    }
}

// ---------------- fp32 butterflies + passes (kA only) ------------------------
template <bool INV>
__device__ __forceinline__ void bfly4(float2* x) {
    float t0r = x[0].x + x[2].x, t0i = x[0].y + x[2].y;
    float t1r = x[0].x - x[2].x, t1i = x[0].y - x[2].y;
    float t2r = x[1].x + x[3].x, t2i = x[1].y + x[3].y;
    float t3r = x[1].x - x[3].x, t3i = x[1].y - x[3].y;
    x[0].x = t0r + t2r; x[0].y = t0i + t2i;
    x[2].x = t0r - t2r; x[2].y = t0i - t2i;
    if (!INV) {
        x[1].x = t1r + t3i; x[1].y = t1i - t3r;
        x[3].x = t1r - t3i; x[3].y = t1i + t3r;
    } else {
        x[1].x = t1r - t3i; x[1].y = t1i + t3r;
        x[3].x = t1r + t3i; x[3].y = t1i - t3r;
    }
}

template <bool INV>
__device__ __forceinline__ void bfly8(float2* x) {
    const float C = 0.70710678118654752f;
    float t0r = x[0].x + x[4].x, t0i = x[0].y + x[4].y;
    float t1r = x[0].x - x[4].x, t1i = x[0].y - x[4].y;
    float t2r = x[2].x + x[6].x, t2i = x[2].y + x[6].y;
    float t3r = x[2].x - x[6].x, t3i = x[2].y - x[6].y;
    float e0r = t0r + t2r, e0i = t0i + t2i;
    float e2r = t0r - t2r, e2i = t0i - t2i;
    float e1r, e1i, e3r, e3i;
    if (!INV) { e1r = t1r + t3i; e1i = t1i - t3r; e3r = t1r - t3i; e3i = t1i + t3r; }
    else      { e1r = t1r - t3i; e1i = t1i + t3r; e3r = t1r + t3i; e3i = t1i - t3r; }
    float u0r = x[1].x + x[5].x, u0i = x[1].y + x[5].y;
    float u1r = x[1].x - x[5].x, u1i = x[1].y - x[5].y;
    float u2r = x[3].x + x[7].x, u2i = x[3].y + x[7].y;
    float u3r = x[3].x - x[7].x, u3i = x[3].y - x[7].y;
    float o0r = u0r + u2r, o0i = u0i + u2i;
    float o2r = u0r - u2r, o2i = u0i - u2i;
    float o1r, o1i, o3r, o3i;
    if (!INV) { o1r = u1r + u3i; o1i = u1i - u3r; o3r = u1r - u3i; o3i = u1i + u3r; }
    else      { o1r = u1r - u3i; o1i = u1i + u3r; o3r = u1r + u3i; o3i = u1i - u3r; }
    float w1r, w1i, w2r, w2i, w3r, w3i;
    if (!INV) {
        w1r = C * (o1r + o1i); w1i = C * (o1i - o1r);
        w2r = o2i;             w2i = -o2r;
        w3r = C * (o3i - o3r); w3i = -C * (o3r + o3i);
    } else {
        w1r = C * (o1r - o1i); w1i = C * (o1i + o1r);
        w2r = -o2i;            w2i = o2r;
        w3r = -C * (o3r + o3i); w3i = C * (o3r - o3i);
    }
    x[0].x = e0r + o0r; x[0].y = e0i + o0i;
    x[1].x = e1r + w1r; x[1].y = e1i + w1i;
    x[2].x = e2r + w2r; x[2].y = e2i + w2i;
    x[3].x = e3r + w3r; x[3].y = e3i + w3i;
    x[4].x = e0r - o0r; x[4].y = e0i - o0i;
    x[5].x = e1r - w1r; x[5].y = e1i - w1i;
    x[6].x = e2r - w2r; x[6].y = e2i - w2i;
    x[7].x = e3r - w3r; x[7].y = e3i - w3i;
}

template <bool INV>
__device__ __forceinline__ void comb_regs(float2* x, const float* twr, const float* twi) {
    if (!INV) {
#pragma unroll
        for (int j = 0; j < 4; j++) {
            float2 y[4];
#pragma unroll
            for (int k = 0; k < 4; k++) y[k] = x[j + 4 * k];
            bfly4<false>(y);
#pragma unroll
            for (int k = 1; k < 4; k++) {
                int ti = 8 * j * k;
                float wr = twr[ti], wi = twi[ti];
                float a = y[k].x, b = y[k].y;
                y[k].x = a * wr - b * wi; y[k].y = a * wi + b * wr;
            }
#pragma unroll
            for (int k = 0; k < 4; k++) x[j + 4 * k] = y[k];
        }
#pragma unroll
        for (int a = 0; a < 4; a++) bfly4<false>(&x[4 * a]);
    } else {
#pragma unroll
        for (int a = 0; a < 4; a++) bfly4<true>(&x[4 * a]);
#pragma unroll
        for (int j = 0; j < 4; j++) {
            float2 y[4];
#pragma unroll
            for (int k = 0; k < 4; k++) y[k] = x[j + 4 * k];
#pragma unroll
            for (int k = 1; k < 4; k++) {
                int ti = 8 * j * k;
                float wr = twr[ti], wi = -twi[ti];
                float a = y[k].x, b = y[k].y;
                y[k].x = a * wr - b * wi; y[k].y = a * wi + b * wr;
            }
            bfly4<true>(y);
#pragma unroll
            for (int k = 0; k < 4; k++) x[j + 4 * k] = y[k];
        }
    }
}

template <int BS, bool INV, int DIM>
__device__ __forceinline__ void comb_stage(float2* sc, const float* twr, const float* twi) {
    for (int idx = threadIdx.x; idx < 1024; idx += BS) {
        int q = idx & 127, g = idx >> 7;
        int base = (DIM == 0) ? q * NPAD + (g << 4) : (g << 4) * NPAD + q;
        int step = (DIM == 0) ? 1 : NPAD;
        float2 x[16];
#pragma unroll
        for (int m = 0; m < 16; m++) x[m] = sc[base + m * step];
        comb_regs<INV>(x, twr, twi);
#pragma unroll
        for (int m = 0; m < 16; m++) sc[base + m * step] = x[m];
    }
    __syncthreads();
}

template <int BS, bool INV, int DIM>
__device__ __forceinline__ void r8_stage(float2* sc, const float* twr, const float* twi) {
    for (int idx = threadIdx.x; idx < 2048; idx += BS) {
        int q = idx & 127, j = idx >> 7;
        int base = (DIM == 0) ? q * NPAD + j : j * NPAD + q;
        int step = (DIM == 0) ? 16 : 16 * NPAD;
        float2 x[8];
#pragma unroll
        for (int k = 0; k < 8; k++) x[k] = sc[base + k * step];
        if (INV) {
#pragma unroll
            for (int k = 1; k < 8; k++) {
                int t = j * k;
                float wr = twr[t], wi = -twi[t];
                float a = x[k].x, b = x[k].y;
                x[k].x = a * wr - b * wi; x[k].y = a * wi + b * wr;
            }
        }
        bfly8<INV>(x);
        if (!INV) {
#pragma unroll
            for (int k = 1; k < 8; k++) {
                int t = j * k;
                float wr = twr[t], wi = twi[t];
                float a = x[k].x, b = x[k].y;
                x[k].x = a * wr - b * wi; x[k].y = a * wi + b * wr;
            }
        }
#pragma unroll
        for (int k = 0; k < 8; k++) sc[base + k * step] = x[k];
    }
    __syncthreads();
}

#define INIT_TWIDDLES_F32()                                                    \
    do {                                                                       \
        if (threadIdx.x < 128) {                                               \
            float sv, cv;                                                      \
            __sincosf(-2.f * PI_F * (float)threadIdx.x / 128.f, &sv, &cv);     \
            s_twr[threadIdx.x] = cv;                                           \
            s_twi[threadIdx.x] = sv;                                           \
        }                                                                      \
    } while (0)

// packed twiddle tables: wc=(c,c); wdf=(-d,d) fwd; wdi=(d,-d) inv; w=(c,d)=e^{-i2pi t/128}
#define INIT_TWIDDLES_PK()                                                     \
    do {                                                                       \
        if (threadIdx.x < 128) {                                               \
            float sv, cv;                                                      \
            __sincosf(-2.f * PI_F * (float)threadIdx.x / 128.f, &sv, &cv);     \
            s_wc [threadIdx.x] = pk2(cv, cv);                                  \
            s_wdf[threadIdx.x] = pk2(-sv, sv);                                 \
            s_wdi[threadIdx.x] = pk2(sv, -sv);                                 \
        }                                                                      \
    } while (0)

// warp-shuffle block reduction (deterministic); result valid in tid 0
template <int BS>
__device__ __forceinline__ float block_sum(float v, float* red) {
#pragma unroll
    for (int o = 16; o; o >>= 1) v += __shfl_xor_sync(0xffffffffu, v, o);
    if ((threadIdx.x & 31) == 0) red[threadIdx.x >> 5] = v;
    __syncthreads();
    float s = 0.f;
    if (threadIdx.x < 32) {
        s = (threadIdx.x < BS / 32) ? red[threadIdx.x] : 0.f;
#pragma unroll
        for (int o = 16; o; o >>= 1) s += __shfl_xor_sync(0xffffffffu, s, o);
    }
    return s;
}

// ---------------- stage A: i_hat = FFT2(image), s0 (fp32) --------------------
__global__ __launch_bounds__(NT, 1) void kA(const float* __restrict__ img) {
    extern __shared__ float2 sc[];
    __shared__ float s_twr[128], s_twi[128];
    __shared__ float red[32];
    int b = blockIdx.x;
    int tid = threadIdx.x;
    INIT_TWIDDLES_F32();

    float local = 0.f;
    for (int idx = tid; idx < 16384; idx += NT) {
        float v = img[b * 16384 + idx];
        int r = idx >> 7, c = idx & 127;
        sc[r * NPAD + c] = make_float2(v, 0.f);
        local += v;
    }
    float s = block_sum<NT>(local, red);
    if (tid == 0) g_s0[b] = s * (1.f / 16384.f);
    __syncthreads();

    r8_stage<NT, false, 0>(sc, s_twr, s_twi);
    comb_stage<NT, false, 0>(sc, s_twr, s_twi);
    r8_stage<NT, false, 1>(sc, s_twr, s_twi);
    comb_stage<NT, false, 1>(sc, s_twr, s_twi);

    for (int idx = tid; idx < 16384; idx += NT) {
        int r = idx >> 7, c = idx & 127;
        g_ihat[b * 16384 + idx] = sc[r * NPAD + c];
    }
}

// ---------------- stage B: u1 = |ifft2(i_hat*psi)|, s1 partial, u1_hat -------
__global__ __launch_bounds__(NT, 2) void kB() {
    extern __shared__ __half2 shb[];
    __shared__ u64 s_wc[128], s_wdf[128], s_wdi[128];
    __shared__ float red[32];
    int bi = blockIdx.x;              // b*16 + j1*4 + l1
    int b  = bi >> 4;
    int j1 = (bi >> 2) & 3;
    int tid = threadIdx.x;
    INIT_TWIDDLES_PK();
    __syncthreads();

    const float2* src = g_ihat + (size_t)b * 16384;
    const float*  psi1 = g_psi + (((size_t)(bi & 15)) << 14);

    hpass_load_inv0_f32<NT>(shb, src, psi1, s_wc, s_wdi);    // inv dim0: comb16
    hr8_stage<NT, true, 0>(shb, s_wc, s_wdi);                // inv dim0: r8
    hcomb_stage<NT, true, 1>(shb, s_wc, s_wdi);              // inv dim1: comb16
    float local = hpass_inv1_r8_mag<NT, true>(shb, s_wc, s_wdi); // inv dim1: r8+mag
    float s = block_sum<NT>(local, red);
    if (tid == 0) g_s1part[bi] = s;
    __syncthreads();

    if (j1 < 3) {                     // j1 == 3 never consumed by second order
        hr8_stage<NT, false, 0>(shb, s_wc, s_wdf);
        hcomb_stage<NT, false, 0>(shb, s_wc, s_wdf);
        hr8_stage<NT, false, 1>(shb, s_wc, s_wdf);
        hpass_fwd1_store<NT>(shb, g_u1hat + (size_t)bi * 16384, s_wc, s_wdf);
    }
}

// ---------------- stage C: fp16-smem, f32x2-compute 4-pass inverse + |.| -----
__global__ __launch_bounds__(NT, 2) void kC() {
    extern __shared__ __half2 sh[];
    __shared__ u64 s_wc[128], s_wdf[128], s_wdi[128];
    __shared__ float red[32];
    int bi = blockIdx.x;              // b*96 + pair*16 + l1*4 + l2
    int b    = bi / 96;
    int r96  = bi % 96;
    int pair = r96 >> 4;
    int l1   = (r96 >> 2) & 3;
    int l2   = r96 & 3;
    const int J1[6] = {0, 0, 0, 1, 1, 2};
    const int J2[6] = {1, 2, 3, 2, 3, 3};
    int j1 = J1[pair], j2 = J2[pair];
    int tid = threadIdx.x;
    INIT_TWIDDLES_PK();
    __syncthreads();

    const __half2* src = g_u1hat + (((size_t)b * 16 + j1 * 4 + l1) << 14);
    const __half*  psi = g_psih + (((size_t)j2 * 4 + l2) << 14);

    // ---- C1: gmem(half) load * psih(pre-scaled) -> comb16 inv dim0 -> smem --
#pragma unroll
    for (int it = 0; it < 2; it++) {
        int idx = tid + it * NT;
        int rr = idx & 127, g = idx >> 7;
        const uint4* s4 = reinterpret_cast<const uint4*>(src + rr * 128 + (g << 4));
        const uint4* p4 = reinterpret_cast<const uint4*>(psi + rr * 128 + (g << 4));
        uint4 svv[4] = {s4[0], s4[1], s4[2], s4[3]};
        uint4 pvv[2] = {p4[0], p4[1]};
        const __half2* sh2 = reinterpret_cast<const __half2*>(svv);
        const __half*  ph  = reinterpret_cast<const __half*>(pvv);
        u64 x[16];
#pragma unroll
        for (int m = 0; m < 16; m++) {
            float2 v = __half22float2(sh2[m]);
            float  p = __half2float(ph[m]);
            x[m] = pk2(v.x * p, v.y * p);
        }
        comb_regsp<true>(x, s_wc, s_wdi);
        int base = rr * SPAD + (g << 4);
#pragma unroll
        for (int m = 0; m < 16; m++) sh[base + m] = cvt_st(x[m]);
    }
    __syncthreads();

    hr8_stage<NT, true, 0>(sh, s_wc, s_wdi);                  // inv dim0: r8
    hcomb_stage<NT, true, 1>(sh, s_wc, s_wdi);                // inv dim1: comb16
    float local = hpass_inv1_r8_mag<NT, false>(sh, s_wc, s_wdi); // inv dim1: r8+|.|
    float s = block_sum<NT>(local, red);
    if (tid == 0) g_s2part[bi] = s;
}

// ---------------- stage D: deterministic reduce + MLP ------------------------
__global__ void kD(const float* __restrict__ fc1w, const float* __restrict__ fc1b,
                   const float* __restrict__ fc2w, const float* __restrict__ fc2b,
                   float* __restrict__ out) {
    int b = threadIdx.x;
    if (b >= 64) return;
    float s[11];
    s[0] = g_s0[b];
    for (int j = 0; j < 4; j++) {
        float acc = 0.f;
        for (int l = 0; l < 4; l++) acc += g_s1part[b * 16 + j * 4 + l];
        s[1 + j] = acc * (1.f / (4.f * 16384.f));
    }
    for (int p = 0; p < 6; p++) {
        float acc = 0.f;
        for (int kk = 0; kk < 16; kk++) acc += g_s2part[b * 96 + p * 16 + kk];
        s[5 + p] = acc * (1.f / (16.f * 16384.f));
    }
    float h[4];
    for (int i = 0; i < 4; i++) {
        float a = fc1b[i];
        for (int t = 0; t < 11; t++) a += fc1w[i * 11 + t] * s[t];
        h[i] = fmaxf(a, 0.f);
    }
    for (int kk = 0; kk < 10; kk++) {
        float a = fc2b[kk];
        for (int i = 0; i < 4; i++) a += fc2w[kk * 4 + i] * h[i];
        out[b * 10 + kk] = 1.f / (1.f + expf(-a));
    }
}

// ---------------- launch -----------------------------------------------------
extern "C" void kernel_launch(void* const* d_in, const int* in_sizes, int n_in,
                              void* d_out, int out_size) {
    const float* img  = (const float*)d_in[0];
    const float* fc1w = (const float*)d_in[1];
    const float* fc1b = (const float*)d_in[2];
    const float* fc2w = (const float*)d_in[3];
    const float* fc2b = (const float*)d_in[4];
    float* out = (float*)d_out;

    const size_t smemA  = 128 * NPAD * sizeof(float2);   // 132096 B
    const size_t smemBC = 128 * SPAD * sizeof(__half2);  // 66048 B (2 CTAs/SM)
    cudaFuncSetAttribute(kA, cudaFuncAttributeMaxDynamicSharedMemorySize, (int)smemA);
    cudaFuncSetAttribute(kB, cudaFuncAttributeMaxDynamicSharedMemorySize, (int)smemBC);
    cudaFuncSetAttribute(kC, cudaFuncAttributeMaxDynamicSharedMemorySize, (int)smemBC);

    init_psi_kernel<<<256, 1024>>>();
    kA<<<64, NT, smemA>>>(img);
    kB<<<1024, NT, smemBC>>>();
    kC<<<6144, NT, smemBC>>>();
    kD<<<1, 64>>>(fc1w, fc1b, fc2w, fc2b, out);
}

// round 16
// speedup vs baseline: 1.6611x; 1.1734x over previous
#include <cuda_runtime.h>
#include <cuda_fp16.h>
#include <math.h>

#define NPAD 129     // fp32 smem layout (kA), float2 units
#define SPAD 129     // fp16 smem layout (kB/kC), half2 units
#define NT   512
#define PI_F 3.14159265358979f

// ---------------- device scratch (static: no allocation allowed) -------------
__device__ float2  g_ihat [64  * 16384];   // FFT2(image), digit-rev layout (fp32)
__device__ __half2 g_u1hat[1024 * 16384];  // FFT2(|u1|),  digit-rev layout (fp16)
__device__ float   g_psi  [16  * 16384];   // Morlet bank, digit-rev (fp32, kB)
__device__ __half  g_psih [16  * 16384];   // Morlet bank, digit-rev (fp16*scale, kC)
__device__ float   g_s0   [64];
__device__ float   g_s1part[1024];
__device__ float   g_s2part[6144];

// digit-reversal for radix [8,4,4] DIF: freq f -> storage position
__device__ __forceinline__ int dperm(int f) {
    return ((f & 7) << 4) | (((f >> 3) & 3) << 2) | (f >> 5);
}

// ---------------- filter bank, stored pre-permuted ---------------------------
__global__ void init_psi_kernel() {
    int idx = blockIdx.x * blockDim.x + threadIdx.x;
    if (idx >= 16 * 16384) return;
    int fc = idx & 127;
    int fr = (idx >> 7) & 127;
    int l  = (idx >> 14) & 3;
    int j  = idx >> 16;
    const float w = 2.f * PI_F / 128.f;
    float fx = (float)((fr < 64) ? fr : fr - 128) * w;
    float fy = (float)((fc < 64) ? fc : fc - 128) * w;
    float k0 = (3.f * PI_F / 4.f) / (float)(1 << j);
    float sg = 0.8f * (float)(1 << j);
    float th = PI_F * (float)l / 4.f;
    float k0x = k0 * cosf(th), k0y = k0 * sinf(th);
    float hs = 0.5f * sg * sg;
    float beta = expf(-hs * k0 * k0);
    float gs = expf(-hs * ((fx - k0x) * (fx - k0x) + (fy - k0y) * (fy - k0y)));
    float g0 = expf(-hs * (fx * fx + fy * fy));
    float v = gs - beta * g0;
    int pos = ((j * 4 + l) << 14) + (dperm(fr) << 7) + dperm(fc);
    g_psi[pos]  = v;
    g_psih[pos] = __float2half(v * (1.f / 16384.f));  // pre-scaled for kC
}

// ---------------- fp32 register butterflies ----------------------------------
template <bool INV>
__device__ __forceinline__ void bfly4(float2* x) {
    float t0r = x[0].x + x[2].x, t0i = x[0].y + x[2].y;
    float t1r = x[0].x - x[2].x, t1i = x[0].y - x[2].y;
    float t2r = x[1].x + x[3].x, t2i = x[1].y + x[3].y;
    float t3r = x[1].x - x[3].x, t3i = x[1].y - x[3].y;
    x[0].x = t0r + t2r; x[0].y = t0i + t2i;
    x[2].x = t0r - t2r; x[2].y = t0i - t2i;
    if (!INV) {
        x[1].x = t1r + t3i; x[1].y = t1i - t3r;
        x[3].x = t1r - t3i; x[3].y = t1i + t3r;
    } else {
        x[1].x = t1r - t3i; x[1].y = t1i + t3r;
        x[3].x = t1r + t3i; x[3].y = t1i - t3r;
    }
}

template <bool INV>
__device__ __forceinline__ void bfly8(float2* x) {
    const float C = 0.70710678118654752f;
    float t0r = x[0].x + x[4].x, t0i = x[0].y + x[4].y;
    float t1r = x[0].x - x[4].x, t1i = x[0].y - x[4].y;
    float t2r = x[2].x + x[6].x, t2i = x[2].y + x[6].y;
    float t3r = x[2].x - x[6].x, t3i = x[2].y - x[6].y;
    float e0r = t0r + t2r, e0i = t0i + t2i;
    float e2r = t0r - t2r, e2i = t0i - t2i;
    float e1r, e1i, e3r, e3i;
    if (!INV) { e1r = t1r + t3i; e1i = t1i - t3r; e3r = t1r - t3i; e3i = t1i + t3r; }
    else      { e1r = t1r - t3i; e1i = t1i + t3r; e3r = t1r + t3i; e3i = t1i - t3r; }
    float u0r = x[1].x + x[5].x, u0i = x[1].y + x[5].y;
    float u1r = x[1].x - x[5].x, u1i = x[1].y - x[5].y;
    float u2r = x[3].x + x[7].x, u2i = x[3].y + x[7].y;
    float u3r = x[3].x - x[7].x, u3i = x[3].y - x[7].y;
    float o0r = u0r + u2r, o0i = u0i + u2i;
    float o2r = u0r - u2r, o2i = u0i - u2i;
    float o1r, o1i, o3r, o3i;
    if (!INV) { o1r = u1r + u3i; o1i = u1i - u3r; o3r = u1r - u3i; o3i = u1i + u3r; }
    else      { o1r = u1r - u3i; o1i = u1i + u3r; o3r = u1r + u3i; o3i = u1i - u3r; }
    float w1r, w1i, w2r, w2i, w3r, w3i;
    if (!INV) {
        w1r = C * (o1r + o1i); w1i = C * (o1i - o1r);
        w2r = o2i;             w2i = -o2r;
        w3r = C * (o3i - o3r); w3i = -C * (o3r + o3i);
    } else {
        w1r = C * (o1r - o1i); w1i = C * (o1i + o1r);
        w2r = -o2i;            w2i = o2r;
        w3r = -C * (o3r + o3i); w3i = C * (o3r - o3i);
    }
    x[0].x = e0r + o0r; x[0].y = e0i + o0i;
    x[1].x = e1r + w1r; x[1].y = e1i + w1i;
    x[2].x = e2r + w2r; x[2].y = e2i + w2i;
    x[3].x = e3r + w3r; x[3].y = e3i + w3i;
    x[4].x = e0r - o0r; x[4].y = e0i - o0i;
    x[5].x = e1r - w1r; x[5].y = e1i - w1i;
    x[6].x = e2r - w2r; x[6].y = e2i - w2i;
    x[7].x = e3r - w3r; x[7].y = e3i - w3i;
}

// twiddle index map for comb stages: t = 8*j*k, j,k in 1..3 -> j*k in {1,2,3,4,6,9}
__device__ __forceinline__ constexpr int t6map(int jk) {
    return (jk == 1) ? 0 : (jk == 2) ? 1 : (jk == 3) ? 2 :
           (jk == 4) ? 3 : (jk == 6) ? 4 : 5;
}

// combined [r4-mid (stride4) + r4-last (stride1)] on 16 register points.
// tw6 = 6 preloaded twiddles (cos,sin of -2pi*8m/128 for m in {1,2,3,4,6,9})
template <bool INV>
__device__ __forceinline__ void comb_regs(float2* x, const float2* tw6) {
    if (!INV) {
#pragma unroll
        for (int j = 0; j < 4; j++) {
            float2 y[4];
#pragma unroll
            for (int k = 0; k < 4; k++) y[k] = x[j + 4 * k];
            bfly4<false>(y);
            if (j > 0) {
#pragma unroll
                for (int k = 1; k < 4; k++) {
                    float2 w = tw6[t6map(j * k)];
                    float a = y[k].x, b = y[k].y;
                    y[k].x = a * w.x - b * w.y; y[k].y = a * w.y + b * w.x;
                }
            }
#pragma unroll
            for (int k = 0; k < 4; k++) x[j + 4 * k] = y[k];
        }
#pragma unroll
        for (int a = 0; a < 4; a++) bfly4<false>(&x[4 * a]);
    } else {
#pragma unroll
        for (int a = 0; a < 4; a++) bfly4<true>(&x[4 * a]);
#pragma unroll
        for (int j = 0; j < 4; j++) {
            float2 y[4];
#pragma unroll
            for (int k = 0; k < 4; k++) y[k] = x[j + 4 * k];
            if (j > 0) {
#pragma unroll
                for (int k = 1; k < 4; k++) {
                    float2 w = tw6[t6map(j * k)];
                    float a = y[k].x, b = y[k].y;
                    y[k].x = a * w.x + b * w.y; y[k].y = -a * w.y + b * w.x;
                }
            }
            bfly4<true>(y);
#pragma unroll
            for (int k = 0; k < 4; k++) x[j + 4 * k] = y[k];
        }
    }
}

// preload the 6 comb twiddles from the shared fp32 tables
#define LOAD_TW6(tw6, twr, twi)                                                \
    do {                                                                       \
        const int T6[6] = {8, 16, 24, 32, 48, 72};                             \
        _Pragma("unroll")                                                      \
        for (int m = 0; m < 6; m++)                                            \
            tw6[m] = make_float2((twr)[T6[m]], (twi)[T6[m]]);                  \
    } while (0)

// ---------------- fp32 smem passes (kA only) ---------------------------------
template <int BS, bool INV, int DIM>
__device__ __forceinline__ void comb_stage(float2* sc, const float2* tw6) {
    for (int idx = threadIdx.x; idx < 1024; idx += BS) {
        int q = idx & 127, g = idx >> 7;
        int base = (DIM == 0) ? q * NPAD + (g << 4) : (g << 4) * NPAD + q;
        int step = (DIM == 0) ? 1 : NPAD;
        float2 x[16];
#pragma unroll
        for (int m = 0; m < 16; m++) x[m] = sc[base + m * step];
        comb_regs<INV>(x, tw6);
#pragma unroll
        for (int m = 0; m < 16; m++) sc[base + m * step] = x[m];
    }
    __syncthreads();
}

template <int BS, bool INV, int DIM>
__device__ __forceinline__ void r8_stage(float2* sc, const float* twr, const float* twi) {
    int j = threadIdx.x >> 5;          // 0..15 fixed per thread (BS=512)
    int lane = threadIdx.x & 31;
    float wr_[8], wi_[8];
#pragma unroll
    for (int k = 1; k < 8; k++) {
        int t = j * k;
        wr_[k] = twr[t];
        wi_[k] = INV ? -twi[t] : twi[t];
    }
#pragma unroll
    for (int it = 0; it < 4; it++) {
        int q = lane + (it << 5);
        int base = (DIM == 0) ? q * NPAD + j : j * NPAD + q;
        int step = (DIM == 0) ? 16 : 16 * NPAD;
        float2 x[8];
#pragma unroll
        for (int k = 0; k < 8; k++) x[k] = sc[base + k * step];
        if (INV) {
#pragma unroll
            for (int k = 1; k < 8; k++) {
                float a = x[k].x, b = x[k].y;
                x[k].x = a * wr_[k] - b * wi_[k]; x[k].y = a * wi_[k] + b * wr_[k];
            }
        }
        bfly8<INV>(x);
        if (!INV) {
#pragma unroll
            for (int k = 1; k < 8; k++) {
                float a = x[k].x, b = x[k].y;
                x[k].x = a * wr_[k] - b * wi_[k]; x[k].y = a * wi_[k] + b * wr_[k];
            }
        }
#pragma unroll
        for (int k = 0; k < 8; k++) sc[base + k * step] = x[k];
    }
    __syncthreads();
}

// ---------------- fp16-storage smem passes (kB / kC) -------------------------
template <int BS, bool INV, int DIM>
__device__ __forceinline__ void hcomb_stage(__half2* sh, const float2* tw6) {
    for (int idx = threadIdx.x; idx < 1024; idx += BS) {
        int q = idx & 127, g = idx >> 7;
        int base = (DIM == 0) ? q * SPAD + (g << 4) : (g << 4) * SPAD + q;
        int step = (DIM == 0) ? 1 : SPAD;
        float2 x[16];
#pragma unroll
        for (int m = 0; m < 16; m++) x[m] = __half22float2(sh[base + m * step]);
        comb_regs<INV>(x, tw6);
#pragma unroll
        for (int m = 0; m < 16; m++) sh[base + m * step] = __float22half2_rn(x[m]);
    }
    __syncthreads();
}

template <int BS, bool INV, int DIM>
__device__ __forceinline__ void hr8_stage(__half2* sh, const float* twr, const float* twi) {
    int j = threadIdx.x >> 5;          // fixed per thread
    int lane = threadIdx.x & 31;
    float wr_[8], wi_[8];
#pragma unroll
    for (int k = 1; k < 8; k++) {
        int t = j * k;
        wr_[k] = twr[t];
        wi_[k] = INV ? -twi[t] : twi[t];
    }
#pragma unroll
    for (int it = 0; it < 4; it++) {
        int q = lane + (it << 5);
        int base = (DIM == 0) ? q * SPAD + j : j * SPAD + q;
        int step = (DIM == 0) ? 16 : 16 * SPAD;
        float2 x[8];
#pragma unroll
        for (int k = 0; k < 8; k++) x[k] = __half22float2(sh[base + k * step]);
        if (INV) {
#pragma unroll
            for (int k = 1; k < 8; k++) {
                float a = x[k].x, b = x[k].y;
                x[k].x = a * wr_[k] - b * wi_[k]; x[k].y = a * wi_[k] + b * wr_[k];
            }
        }
        bfly8<INV>(x);
        if (!INV) {
#pragma unroll
            for (int k = 1; k < 8; k++) {
                float a = x[k].x, b = x[k].y;
                x[k].x = a * wr_[k] - b * wi_[k]; x[k].y = a * wi_[k] + b * wr_[k];
            }
        }
#pragma unroll
        for (int k = 0; k < 8; k++) sh[base + k * step] = __float22half2_rn(x[k]);
    }
    __syncthreads();
}

// kB entry: (fp32 gmem src * fp32 psi * scale) -> comb inv dim0 -> half2 smem
template <int BS>
__device__ __forceinline__ void hpass_load_inv0_f32(__half2* sh, const float2* __restrict__ src,
                                                    const float* __restrict__ psi,
                                                    const float2* tw6) {
    const float scale = 1.f / 16384.f;
    for (int idx = threadIdx.x; idx < 1024; idx += BS) {
        int rr = idx & 127, g = idx >> 7;
        int gbase = rr * 128 + (g << 4);
        const float4* s4 = reinterpret_cast<const float4*>(src + gbase);
        const float4* p4 = reinterpret_cast<const float4*>(psi + gbase);
        float2 x[16];
#pragma unroll
        for (int m8 = 0; m8 < 4; m8++) {
            float4 p = p4[m8];
            float4 v0 = s4[m8 * 2], v1 = s4[m8 * 2 + 1];
            float pa = p.x * scale, pb = p.y * scale, pc = p.z * scale, pd = p.w * scale;
            x[m8 * 4 + 0] = make_float2(v0.x * pa, v0.y * pa);
            x[m8 * 4 + 1] = make_float2(v0.z * pb, v0.w * pb);
            x[m8 * 4 + 2] = make_float2(v1.x * pc, v1.y * pc);
            x[m8 * 4 + 3] = make_float2(v1.z * pd, v1.w * pd);
        }
        comb_regs<true>(x, tw6);
        int base = rr * SPAD + (g << 4);
#pragma unroll
        for (int m = 0; m < 16; m++) sh[base + m] = __float22half2_rn(x[m]);
    }
    __syncthreads();
}

// final inverse r8 dim1 + |.|; optionally write mag back as half2(mag,0)
template <int BS, bool WRITE>
__device__ __forceinline__ float hpass_inv1_r8_mag(__half2* sh, const float* twr, const float* twi) {
    int j = threadIdx.x >> 5;
    int lane = threadIdx.x & 31;
    float wr_[8], wi_[8];
#pragma unroll
    for (int k = 1; k < 8; k++) {
        int t = j * k;
        wr_[k] = twr[t];
        wi_[k] = -twi[t];
    }
    float local = 0.f;
#pragma unroll
    for (int it = 0; it < 4; it++) {
        int q = lane + (it << 5);
        int base = j * SPAD + q;
        int step = 16 * SPAD;
        float2 x[8];
#pragma unroll
        for (int k = 0; k < 8; k++) x[k] = __half22float2(sh[base + k * step]);
#pragma unroll
        for (int k = 1; k < 8; k++) {
            float a = x[k].x, b = x[k].y;
            x[k].x = a * wr_[k] - b * wi_[k]; x[k].y = a * wi_[k] + b * wr_[k];
        }
        bfly8<true>(x);
#pragma unroll
        for (int k = 0; k < 8; k++) {
            float mag = sqrtf(x[k].x * x[k].x + x[k].y * x[k].y);
            local += mag;
            if (WRITE) sh[base + k * step] = __floats2half2_rn(mag, 0.f);
        }
    }
    __syncthreads();
    return local;
}

// final forward comb dim1 -> gmem half2 store (coalesced per leg)
template <int BS>
__device__ __forceinline__ void hpass_fwd1_store(__half2* sh, __half2* __restrict__ dst,
                                                 const float2* tw6) {
    for (int idx = threadIdx.x; idx < 1024; idx += BS) {
        int q = idx & 127, g = idx >> 7;
        int base = (g << 4) * SPAD + q;
        float2 x[16];
#pragma unroll
        for (int m = 0; m < 16; m++) x[m] = __half22float2(sh[base + m * SPAD]);
        comb_regs<false>(x, tw6);
#pragma unroll
        for (int m = 0; m < 16; m++)
            dst[((g << 4) + m) * 128 + q] = __float22half2_rn(x[m]);
    }
}

#define INIT_TWIDDLES()                                                        \
    do {                                                                       \
        if (threadIdx.x < 128) {                                               \
            float sv, cv;                                                      \
            __sincosf(-2.f * PI_F * (float)threadIdx.x / 128.f, &sv, &cv);     \
            s_twr[threadIdx.x] = cv;                                           \
            s_twi[threadIdx.x] = sv;                                           \
        }                                                                      \
    } while (0)

// warp-shuffle block reduction (deterministic); result valid in tid 0
template <int BS>
__device__ __forceinline__ float block_sum(float v, float* red) {
#pragma unroll
    for (int o = 16; o; o >>= 1) v += __shfl_xor_sync(0xffffffffu, v, o);
    if ((threadIdx.x & 31) == 0) red[threadIdx.x >> 5] = v;
    __syncthreads();
    float s = 0.f;
    if (threadIdx.x < 32) {
        s = (threadIdx.x < BS / 32) ? red[threadIdx.x] : 0.f;
#pragma unroll
        for (int o = 16; o; o >>= 1) s += __shfl_xor_sync(0xffffffffu, s, o);
    }
    return s;
}

// ---------------- stage A: i_hat = FFT2(image), s0 (fp32) --------------------
__global__ __launch_bounds__(NT, 1) void kA(const float* __restrict__ img) {
    extern __shared__ float2 sc[];
    __shared__ float s_twr[128], s_twi[128];
    __shared__ float red[32];
    int b = blockIdx.x;
    int tid = threadIdx.x;
    INIT_TWIDDLES();

    float local = 0.f;
    for (int idx = tid; idx < 16384; idx += NT) {
        float v = img[b * 16384 + idx];
        int r = idx >> 7, c = idx & 127;
        sc[r * NPAD + c] = make_float2(v, 0.f);
        local += v;
    }
    float s = block_sum<NT>(local, red);
    if (tid == 0) g_s0[b] = s * (1.f / 16384.f);
    __syncthreads();

    float2 tw6[6];
    LOAD_TW6(tw6, s_twr, s_twi);

    r8_stage<NT, false, 0>(sc, s_twr, s_twi);
    comb_stage<NT, false, 0>(sc, tw6);
    r8_stage<NT, false, 1>(sc, s_twr, s_twi);
    comb_stage<NT, false, 1>(sc, tw6);

    for (int idx = tid; idx < 16384; idx += NT) {
        int r = idx >> 7, c = idx & 127;
        g_ihat[b * 16384 + idx] = sc[r * NPAD + c];
    }
}

// ---------------- stage B: u1 = |ifft2(i_hat*psi)|, s1 partial, u1_hat -------
__global__ __launch_bounds__(NT, 2) void kB() {
    extern __shared__ __half2 shb[];
    __shared__ float s_twr[128], s_twi[128];
    __shared__ float red[32];
    int bi = blockIdx.x;              // b*16 + j1*4 + l1
    int b  = bi >> 4;
    int j1 = (bi >> 2) & 3;
    int tid = threadIdx.x;
    INIT_TWIDDLES();
    __syncthreads();

    float2 tw6[6];
    LOAD_TW6(tw6, s_twr, s_twi);

    const float2* src = g_ihat + (size_t)b * 16384;
    const float*  psi1 = g_psi + (((size_t)(bi & 15)) << 14);

    hpass_load_inv0_f32<NT>(shb, src, psi1, tw6);            // inv dim0: comb16
    hr8_stage<NT, true, 0>(shb, s_twr, s_twi);               // inv dim0: r8
    hcomb_stage<NT, true, 1>(shb, tw6);                      // inv dim1: comb16
    float local = hpass_inv1_r8_mag<NT, true>(shb, s_twr, s_twi); // inv dim1: r8+mag
    float s = block_sum<NT>(local, red);
    if (tid == 0) g_s1part[bi] = s;
    __syncthreads();

    if (j1 < 3) {                     // j1 == 3 never consumed by second order
        hr8_stage<NT, false, 0>(shb, s_twr, s_twi);
        hcomb_stage<NT, false, 0>(shb, tw6);
        hr8_stage<NT, false, 1>(shb, s_twr, s_twi);
        hpass_fwd1_store<NT>(shb, g_u1hat + (size_t)bi * 16384, tw6);
    }
}

// ---------------- stage C: fp16-smem 4-pass inverse + |.| --------------------
__global__ __launch_bounds__(NT, 2) void kC() {
    extern __shared__ __half2 sh[];
    __shared__ float s_twr[128], s_twi[128];
    __shared__ float red[32];
    int bi = blockIdx.x;              // b*96 + pair*16 + l1*4 + l2
    int b    = bi / 96;
    int r96  = bi % 96;
    int pair = r96 >> 4;
    int l1   = (r96 >> 2) & 3;
    int l2   = r96 & 3;
    const int J1[6] = {0, 0, 0, 1, 1, 2};
    const int J2[6] = {1, 2, 3, 2, 3, 3};
    int j1 = J1[pair], j2 = J2[pair];
    int tid = threadIdx.x;
    INIT_TWIDDLES();
    __syncthreads();

    float2 tw6[6];
    LOAD_TW6(tw6, s_twr, s_twi);

    const __half2* src = g_u1hat + (((size_t)b * 16 + j1 * 4 + l1) << 14);
    const __half*  psi = g_psih + (((size_t)j2 * 4 + l2) << 14);

    // ---- C1: gmem(half) load * psih(pre-scaled) -> comb16 inv dim0 -> smem --
#pragma unroll
    for (int it = 0; it < 2; it++) {
        int idx = tid + it * NT;
        int rr = idx & 127, g = idx >> 7;
        const uint4* s4 = reinterpret_cast<const uint4*>(src + rr * 128 + (g << 4));
        const uint4* p4 = reinterpret_cast<const uint4*>(psi + rr * 128 + (g << 4));
        uint4 svv[4] = {s4[0], s4[1], s4[2], s4[3]};
        uint4 pvv[2] = {p4[0], p4[1]};
        const __half2* sh2 = reinterpret_cast<const __half2*>(svv);
        const __half*  ph  = reinterpret_cast<const __half*>(pvv);
        float2 x[16];
#pragma unroll
        for (int m = 0; m < 16; m++) {
            float2 v = __half22float2(sh2[m]);
            float  p = __half2float(ph[m]);
            x[m] = make_float2(v.x * p, v.y * p);
        }
        comb_regs<true>(x, tw6);
        int base = rr * SPAD + (g << 4);
#pragma unroll
        for (int m = 0; m < 16; m++) sh[base + m] = __float22half2_rn(x[m]);
    }
    __syncthreads();

    hr8_stage<NT, true, 0>(sh, s_twr, s_twi);                 // inv dim0: r8
    hcomb_stage<NT, true, 1>(sh, tw6);                        // inv dim1: comb16
    float local = hpass_inv1_r8_mag<NT, false>(sh, s_twr, s_twi); // inv dim1: r8+|.|
    float s = block_sum<NT>(local, red);
    if (tid == 0) g_s2part[bi] = s;
}

// ---------------- stage D: deterministic reduce + MLP ------------------------
__global__ void kD(const float* __restrict__ fc1w, const float* __restrict__ fc1b,
                   const float* __restrict__ fc2w, const float* __restrict__ fc2b,
                   float* __restrict__ out) {
    int b = threadIdx.x;
    if (b >= 64) return;
    float s[11];
    s[0] = g_s0[b];
    for (int j = 0; j < 4; j++) {
        float acc = 0.f;
        for (int l = 0; l < 4; l++) acc += g_s1part[b * 16 + j * 4 + l];
        s[1 + j] = acc * (1.f / (4.f * 16384.f));
    }
    for (int p = 0; p < 6; p++) {
        float acc = 0.f;
        for (int kk = 0; kk < 16; kk++) acc += g_s2part[b * 96 + p * 16 + kk];
        s[5 + p] = acc * (1.f / (16.f * 16384.f));
    }
    float h[4];
    for (int i = 0; i < 4; i++) {
        float a = fc1b[i];
        for (int t = 0; t < 11; t++) a += fc1w[i * 11 + t] * s[t];
        h[i] = fmaxf(a, 0.f);
    }
    for (int kk = 0; kk < 10; kk++) {
        float a = fc2b[kk];
        for (int i = 0; i < 4; i++) a += fc2w[kk * 4 + i] * h[i];
        out[b * 10 + kk] = 1.f / (1.f + expf(-a));
    }
}

// ---------------- launch -----------------------------------------------------
extern "C" void kernel_launch(void* const* d_in, const int* in_sizes, int n_in,
                              void* d_out, int out_size) {
    const float* img  = (const float*)d_in[0];
    const float* fc1w = (const float*)d_in[1];
    const float* fc1b = (const float*)d_in[2];
    const float* fc2w = (const float*)d_in[3];
    const float* fc2b = (const float*)d_in[4];
    float* out = (float*)d_out;

    const size_t smemA  = 128 * NPAD * sizeof(float2);   // 132096 B
    const size_t smemBC = 128 * SPAD * sizeof(__half2);  // 66048 B (2 CTAs/SM)
    cudaFuncSetAttribute(kA, cudaFuncAttributeMaxDynamicSharedMemorySize, (int)smemA);
    cudaFuncSetAttribute(kB, cudaFuncAttributeMaxDynamicSharedMemorySize, (int)smemBC);
    cudaFuncSetAttribute(kC, cudaFuncAttributeMaxDynamicSharedMemorySize, (int)smemBC);

    init_psi_kernel<<<256, 1024>>>();
    kA<<<64, NT, smemA>>>(img);
    kB<<<1024, NT, smemBC>>>();
    kC<<<6144, NT, smemBC>>>();
    kD<<<1, 64>>>(fc1w, fc1b, fc2w, fc2b, out);
}

// round 17
// speedup vs baseline: 1.7894x; 1.0772x over previous
#include <cuda_runtime.h>
#include <cuda_fp16.h>
#include <math.h>

#define NPAD 129     // fp32 smem layout (kA), float2 units
#define SPAD 129     // fp16 smem layout (kB), half2 units
#define ST1  65      // kC plane row stride (half2 words per c-row)
#define NT   512
#define PI_F 3.14159265358979f

typedef __half2 c16;

// ---------------- device scratch (static: no allocation allowed) -------------
__device__ float2  g_ihat [64  * 16384];   // FFT2(image), digit-rev layout (fp32)
__device__ __half2 g_u1hat[1024 * 16384];  // FFT2(|u1|),  digit-rev layout (fp16)
__device__ float   g_psi  [16  * 16384];   // Morlet bank, digit-rev (fp32, kB)
__device__ __half2 g_psihp[16 * 8192];     // bank pre-scaled, pair-packed (kC)
__device__ float   g_s0   [64];
__device__ float   g_s1part[1024];
__device__ float   g_s2part[6144];

// digit-reversal for radix [8,4,4] DIF: freq f -> storage position
__device__ __forceinline__ int dperm(int f) {
    return ((f & 7) << 4) | (((f >> 3) & 3) << 2) | (f >> 5);
}

// ---------------- filter bank, stored pre-permuted ---------------------------
__global__ void init_psi_kernel() {
    int idx = blockIdx.x * blockDim.x + threadIdx.x;
    if (idx >= 16 * 16384) return;
    int fc = idx & 127;
    int fr = (idx >> 7) & 127;
    int l  = (idx >> 14) & 3;
    int j  = idx >> 16;
    const float w = 2.f * PI_F / 128.f;
    float fx = (float)((fr < 64) ? fr : fr - 128) * w;
    float fy = (float)((fc < 64) ? fc : fc - 128) * w;
    float k0 = (3.f * PI_F / 4.f) / (float)(1 << j);
    float sg = 0.8f * (float)(1 << j);
    float th = PI_F * (float)l / 4.f;
    float k0x = k0 * cosf(th), k0y = k0 * sinf(th);
    float hs = 0.5f * sg * sg;
    float beta = expf(-hs * k0 * k0);
    float gs = expf(-hs * ((fx - k0x) * (fx - k0x) + (fy - k0y) * (fy - k0y)));
    float g0 = expf(-hs * (fx * fx + fy * fy));
    float v = gs - beta * g0;
    int f = j * 4 + l;
    int r = dperm(fr), c = dperm(fc);
    g_psi[(f << 14) + (r << 7) + c] = v;
    // pair-packed, pre-scaled copy for kC: half2 = (psi[2t][c], psi[2t+1][c])
    __half* hp = reinterpret_cast<__half*>(g_psihp);
    hp[(((f * 8 + (c >> 4)) * 64 + (r >> 1)) << 5) + ((c & 15) << 1) + (r & 1)] =
        __float2half(v * (1.f / 16384.f));
}

// ---------------- fp32 register butterflies (kA/kB) --------------------------
template <bool INV>
__device__ __forceinline__ void bfly4(float2* x) {
    float t0r = x[0].x + x[2].x, t0i = x[0].y + x[2].y;
    float t1r = x[0].x - x[2].x, t1i = x[0].y - x[2].y;
    float t2r = x[1].x + x[3].x, t2i = x[1].y + x[3].y;
    float t3r = x[1].x - x[3].x, t3i = x[1].y - x[3].y;
    x[0].x = t0r + t2r; x[0].y = t0i + t2i;
    x[2].x = t0r - t2r; x[2].y = t0i - t2i;
    if (!INV) {
        x[1].x = t1r + t3i; x[1].y = t1i - t3r;
        x[3].x = t1r - t3i; x[3].y = t1i + t3r;
    } else {
        x[1].x = t1r - t3i; x[1].y = t1i + t3r;
        x[3].x = t1r + t3i; x[3].y = t1i - t3r;
    }
}

template <bool INV>
__device__ __forceinline__ void bfly8(float2* x) {
    const float C = 0.70710678118654752f;
    float t0r = x[0].x + x[4].x, t0i = x[0].y + x[4].y;
    float t1r = x[0].x - x[4].x, t1i = x[0].y - x[4].y;
    float t2r = x[2].x + x[6].x, t2i = x[2].y + x[6].y;
    float t3r = x[2].x - x[6].x, t3i = x[2].y - x[6].y;
    float e0r = t0r + t2r, e0i = t0i + t2i;
    float e2r = t0r - t2r, e2i = t0i - t2i;
    float e1r, e1i, e3r, e3i;
    if (!INV) { e1r = t1r + t3i; e1i = t1i - t3r; e3r = t1r - t3i; e3i = t1i + t3r; }
    else      { e1r = t1r - t3i; e1i = t1i + t3r; e3r = t1r + t3i; e3i = t1i - t3r; }
    float u0r = x[1].x + x[5].x, u0i = x[1].y + x[5].y;
    float u1r = x[1].x - x[5].x, u1i = x[1].y - x[5].y;
    float u2r = x[3].x + x[7].x, u2i = x[3].y + x[7].y;
    float u3r = x[3].x - x[7].x, u3i = x[3].y - x[7].y;
    float o0r = u0r + u2r, o0i = u0i + u2i;
    float o2r = u0r - u2r, o2i = u0i - u2i;
    float o1r, o1i, o3r, o3i;
    if (!INV) { o1r = u1r + u3i; o1i = u1i - u3r; o3r = u1r - u3i; o3i = u1i + u3r; }
    else      { o1r = u1r - u3i; o1i = u1i + u3r; o3r = u1r + u3i; o3i = u1i - u3r; }
    float w1r, w1i, w2r, w2i, w3r, w3i;
    if (!INV) {
        w1r = C * (o1r + o1i); w1i = C * (o1i - o1r);
        w2r = o2i;             w2i = -o2r;
        w3r = C * (o3i - o3r); w3i = -C * (o3r + o3i);
    } else {
        w1r = C * (o1r - o1i); w1i = C * (o1i + o1r);
        w2r = -o2i;            w2i = o2r;
        w3r = -C * (o3r + o3i); w3i = C * (o3r - o3i);
    }
    x[0].x = e0r + o0r; x[0].y = e0i + o0i;
    x[1].x = e1r + w1r; x[1].y = e1i + w1i;
    x[2].x = e2r + w2r; x[2].y = e2i + w2i;
    x[3].x = e3r + w3r; x[3].y = e3i + w3i;
    x[4].x = e0r - o0r; x[4].y = e0i - o0i;
    x[5].x = e1r - w1r; x[5].y = e1i - w1i;
    x[6].x = e2r - w2r; x[6].y = e2i - w2i;
    x[7].x = e3r - w3r; x[7].y = e3i - w3i;
}

__device__ __forceinline__ constexpr int t6map(int jk) {
    return (jk == 1) ? 0 : (jk == 2) ? 1 : (jk == 3) ? 2 :
           (jk == 4) ? 3 : (jk == 6) ? 4 : 5;
}

template <bool INV>
__device__ __forceinline__ void comb_regs(float2* x, const float2* tw6) {
    if (!INV) {
#pragma unroll
        for (int j = 0; j < 4; j++) {
            float2 y[4];
#pragma unroll
            for (int k = 0; k < 4; k++) y[k] = x[j + 4 * k];
            bfly4<false>(y);
            if (j > 0) {
#pragma unroll
                for (int k = 1; k < 4; k++) {
                    float2 w = tw6[t6map(j * k)];
                    float a = y[k].x, b = y[k].y;
                    y[k].x = a * w.x - b * w.y; y[k].y = a * w.y + b * w.x;
                }
            }
#pragma unroll
            for (int k = 0; k < 4; k++) x[j + 4 * k] = y[k];
        }
#pragma unroll
        for (int a = 0; a < 4; a++) bfly4<false>(&x[4 * a]);
    } else {
#pragma unroll
        for (int a = 0; a < 4; a++) bfly4<true>(&x[4 * a]);
#pragma unroll
        for (int j = 0; j < 4; j++) {
            float2 y[4];
#pragma unroll
            for (int k = 0; k < 4; k++) y[k] = x[j + 4 * k];
            if (j > 0) {
#pragma unroll
                for (int k = 1; k < 4; k++) {
                    float2 w = tw6[t6map(j * k)];
                    float a = y[k].x, b = y[k].y;
                    y[k].x = a * w.x + b * w.y; y[k].y = -a * w.y + b * w.x;
                }
            }
            bfly4<true>(y);
#pragma unroll
            for (int k = 0; k < 4; k++) x[j + 4 * k] = y[k];
        }
    }
}

#define LOAD_TW6(tw6, twr, twi)                                                \
    do {                                                                       \
        const int T6[6] = {8, 16, 24, 32, 48, 72};                             \
        _Pragma("unroll")                                                      \
        for (int m = 0; m < 6; m++)                                            \
            tw6[m] = make_float2((twr)[T6[m]], (twi)[T6[m]]);                  \
    } while (0)

// ---------------- fp32 smem passes (kA only) ---------------------------------
template <int BS, bool INV, int DIM>
__device__ __forceinline__ void comb_stage(float2* sc, const float2* tw6) {
    for (int idx = threadIdx.x; idx < 1024; idx += BS) {
        int q = idx & 127, g = idx >> 7;
        int base = (DIM == 0) ? q * NPAD + (g << 4) : (g << 4) * NPAD + q;
        int step = (DIM == 0) ? 1 : NPAD;
        float2 x[16];
#pragma unroll
        for (int m = 0; m < 16; m++) x[m] = sc[base + m * step];
        comb_regs<INV>(x, tw6);
#pragma unroll
        for (int m = 0; m < 16; m++) sc[base + m * step] = x[m];
    }
    __syncthreads();
}

template <int BS, bool INV, int DIM>
__device__ __forceinline__ void r8_stage(float2* sc, const float* twr, const float* twi) {
    int j = threadIdx.x >> 5;
    int lane = threadIdx.x & 31;
    float wr_[8], wi_[8];
#pragma unroll
    for (int k = 1; k < 8; k++) {
        int t = j * k;
        wr_[k] = twr[t];
        wi_[k] = INV ? -twi[t] : twi[t];
    }
#pragma unroll
    for (int it = 0; it < 4; it++) {
        int q = lane + (it << 5);
        int base = (DIM == 0) ? q * NPAD + j : j * NPAD + q;
        int step = (DIM == 0) ? 16 : 16 * NPAD;
        float2 x[8];
#pragma unroll
        for (int k = 0; k < 8; k++) x[k] = sc[base + k * step];
        if (INV) {
#pragma unroll
            for (int k = 1; k < 8; k++) {
                float a = x[k].x, b = x[k].y;
                x[k].x = a * wr_[k] - b * wi_[k]; x[k].y = a * wi_[k] + b * wr_[k];
            }
        }
        bfly8<INV>(x);
        if (!INV) {
#pragma unroll
            for (int k = 1; k < 8; k++) {
                float a = x[k].x, b = x[k].y;
                x[k].x = a * wr_[k] - b * wi_[k]; x[k].y = a * wi_[k] + b * wr_[k];
            }
        }
#pragma unroll
        for (int k = 0; k < 8; k++) sc[base + k * step] = x[k];
    }
    __syncthreads();
}

// ---------------- fp16-storage smem passes (kB) ------------------------------
template <int BS, bool INV, int DIM>
__device__ __forceinline__ void hcomb_stage(__half2* sh, const float2* tw6) {
    for (int idx = threadIdx.x; idx < 1024; idx += BS) {
        int q = idx & 127, g = idx >> 7;
        int base = (DIM == 0) ? q * SPAD + (g << 4) : (g << 4) * SPAD + q;
        int step = (DIM == 0) ? 1 : SPAD;
        float2 x[16];
#pragma unroll
        for (int m = 0; m < 16; m++) x[m] = __half22float2(sh[base + m * step]);
        comb_regs<INV>(x, tw6);
#pragma unroll
        for (int m = 0; m < 16; m++) sh[base + m * step] = __float22half2_rn(x[m]);
    }
    __syncthreads();
}

template <int BS, bool INV, int DIM>
__device__ __forceinline__ void hr8_stage(__half2* sh, const float* twr, const float* twi) {
    int j = threadIdx.x >> 5;
    int lane = threadIdx.x & 31;
    float wr_[8], wi_[8];
#pragma unroll
    for (int k = 1; k < 8; k++) {
        int t = j * k;
        wr_[k] = twr[t];
        wi_[k] = INV ? -twi[t] : twi[t];
    }
#pragma unroll
    for (int it = 0; it < 4; it++) {
        int q = lane + (it << 5);
        int base = (DIM == 0) ? q * SPAD + j : j * SPAD + q;
        int step = (DIM == 0) ? 16 : 16 * SPAD;
        float2 x[8];
#pragma unroll
        for (int k = 0; k < 8; k++) x[k] = __half22float2(sh[base + k * step]);
        if (INV) {
#pragma unroll
            for (int k = 1; k < 8; k++) {
                float a = x[k].x, b = x[k].y;
                x[k].x = a * wr_[k] - b * wi_[k]; x[k].y = a * wi_[k] + b * wr_[k];
            }
        }
        bfly8<INV>(x);
        if (!INV) {
#pragma unroll
            for (int k = 1; k < 8; k++) {
                float a = x[k].x, b = x[k].y;
                x[k].x = a * wr_[k] - b * wi_[k]; x[k].y = a * wi_[k] + b * wr_[k];
            }
        }
#pragma unroll
        for (int k = 0; k < 8; k++) sh[base + k * step] = __float22half2_rn(x[k]);
    }
    __syncthreads();
}

template <int BS>
__device__ __forceinline__ void hpass_load_inv0_f32(__half2* sh, const float2* __restrict__ src,
                                                    const float* __restrict__ psi,
                                                    const float2* tw6) {
    const float scale = 1.f / 16384.f;
    for (int idx = threadIdx.x; idx < 1024; idx += BS) {
        int rr = idx & 127, g = idx >> 7;
        int gbase = rr * 128 + (g << 4);
        const float4* s4 = reinterpret_cast<const float4*>(src + gbase);
        const float4* p4 = reinterpret_cast<const float4*>(psi + gbase);
        float2 x[16];
#pragma unroll
        for (int m8 = 0; m8 < 4; m8++) {
            float4 p = p4[m8];
            float4 v0 = s4[m8 * 2], v1 = s4[m8 * 2 + 1];
            float pa = p.x * scale, pb = p.y * scale, pc = p.z * scale, pd = p.w * scale;
            x[m8 * 4 + 0] = make_float2(v0.x * pa, v0.y * pa);
            x[m8 * 4 + 1] = make_float2(v0.z * pb, v0.w * pb);
            x[m8 * 4 + 2] = make_float2(v1.x * pc, v1.y * pc);
            x[m8 * 4 + 3] = make_float2(v1.z * pd, v1.w * pd);
        }
        comb_regs<true>(x, tw6);
        int base = rr * SPAD + (g << 4);
#pragma unroll
        for (int m = 0; m < 16; m++) sh[base + m] = __float22half2_rn(x[m]);
    }
    __syncthreads();
}

template <int BS, bool WRITE>
__device__ __forceinline__ float hpass_inv1_r8_mag(__half2* sh, const float* twr, const float* twi) {
    int j = threadIdx.x >> 5;
    int lane = threadIdx.x & 31;
    float wr_[8], wi_[8];
#pragma unroll
    for (int k = 1; k < 8; k++) {
        int t = j * k;
        wr_[k] = twr[t];
        wi_[k] = -twi[t];
    }
    float local = 0.f;
#pragma unroll
    for (int it = 0; it < 4; it++) {
        int q = lane + (it << 5);
        int base = j * SPAD + q;
        int step = 16 * SPAD;
        float2 x[8];
#pragma unroll
        for (int k = 0; k < 8; k++) x[k] = __half22float2(sh[base + k * step]);
#pragma unroll
        for (int k = 1; k < 8; k++) {
            float a = x[k].x, b = x[k].y;
            x[k].x = a * wr_[k] - b * wi_[k]; x[k].y = a * wi_[k] + b * wr_[k];
        }
        bfly8<true>(x);
#pragma unroll
        for (int k = 0; k < 8; k++) {
            float mag = sqrtf(x[k].x * x[k].x + x[k].y * x[k].y);
            local += mag;
            if (WRITE) sh[base + k * step] = __floats2half2_rn(mag, 0.f);
        }
    }
    __syncthreads();
    return local;
}

template <int BS>
__device__ __forceinline__ void hpass_fwd1_store(__half2* sh, __half2* __restrict__ dst,
                                                 const float2* tw6) {
    for (int idx = threadIdx.x; idx < 1024; idx += BS) {
        int q = idx & 127, g = idx >> 7;
        int base = (g << 4) * SPAD + q;
        float2 x[16];
#pragma unroll
        for (int m = 0; m < 16; m++) x[m] = __half22float2(sh[base + m * SPAD]);
        comb_regs<false>(x, tw6);
#pragma unroll
        for (int m = 0; m < 16; m++)
            dst[((g << 4) + m) * 128 + q] = __float22half2_rn(x[m]);
    }
}

#define INIT_TWIDDLES()                                                        \
    do {                                                                       \
        if (threadIdx.x < 128) {                                               \
            float sv, cv;                                                      \
            __sincosf(-2.f * PI_F * (float)threadIdx.x / 128.f, &sv, &cv);     \
            s_twr[threadIdx.x] = cv;                                           \
            s_twi[threadIdx.x] = sv;                                           \
        }                                                                      \
    } while (0)

// warp-shuffle block reduction (deterministic); result valid in tid 0
template <int BS>
__device__ __forceinline__ float block_sum(float v, float* red) {
#pragma unroll
    for (int o = 16; o; o >>= 1) v += __shfl_xor_sync(0xffffffffu, v, o);
    if ((threadIdx.x & 31) == 0) red[threadIdx.x >> 5] = v;
    __syncthreads();
    float s = 0.f;
    if (threadIdx.x < 32) {
        s = (threadIdx.x < BS / 32) ? red[threadIdx.x] : 0.f;
#pragma unroll
        for (int o = 16; o; o >>= 1) s += __shfl_xor_sync(0xffffffffu, s, o);
    }
    return s;
}

// ============== kC half2-SoA primitives (2 complexes per word) ===============
__device__ __forceinline__ void hcmuls(c16& zr, c16& zi, c16 wr, c16 wi) {
    c16 nr = __hsub2(__hmul2(zr, wr), __hmul2(zi, wi));
    zi = __hfma2(zr, wi, __hmul2(zi, wr));
    zr = nr;
}

__device__ __forceinline__ void hbfly4s_inv(c16* xr, c16* xi) {
    c16 t0r = __hadd2(xr[0], xr[2]), t0i = __hadd2(xi[0], xi[2]);
    c16 t1r = __hsub2(xr[0], xr[2]), t1i = __hsub2(xi[0], xi[2]);
    c16 t2r = __hadd2(xr[1], xr[3]), t2i = __hadd2(xi[1], xi[3]);
    c16 t3r = __hsub2(xr[1], xr[3]), t3i = __hsub2(xi[1], xi[3]);
    xr[0] = __hadd2(t0r, t2r); xi[0] = __hadd2(t0i, t2i);
    xr[2] = __hsub2(t0r, t2r); xi[2] = __hsub2(t0i, t2i);
    xr[1] = __hsub2(t1r, t3i); xi[1] = __hadd2(t1i, t3r);
    xr[3] = __hadd2(t1r, t3i); xi[3] = __hsub2(t1i, t3r);
}

__device__ __forceinline__ void hbfly8s_inv(c16* xr, c16* xi) {
    const c16 C2 = __floats2half2_rn(0.70710678f, 0.70710678f);
    c16 t0r = __hadd2(xr[0], xr[4]), t0i = __hadd2(xi[0], xi[4]);
    c16 t1r = __hsub2(xr[0], xr[4]), t1i = __hsub2(xi[0], xi[4]);
    c16 t2r = __hadd2(xr[2], xr[6]), t2i = __hadd2(xi[2], xi[6]);
    c16 t3r = __hsub2(xr[2], xr[6]), t3i = __hsub2(xi[2], xi[6]);
    c16 e0r = __hadd2(t0r, t2r), e0i = __hadd2(t0i, t2i);
    c16 e2r = __hsub2(t0r, t2r), e2i = __hsub2(t0i, t2i);
    c16 e1r = __hsub2(t1r, t3i), e1i = __hadd2(t1i, t3r);
    c16 e3r = __hadd2(t1r, t3i), e3i = __hsub2(t1i, t3r);
    c16 u0r = __hadd2(xr[1], xr[5]), u0i = __hadd2(xi[1], xi[5]);
    c16 u1r = __hsub2(xr[1], xr[5]), u1i = __hsub2(xi[1], xi[5]);
    c16 u2r = __hadd2(xr[3], xr[7]), u2i = __hadd2(xi[3], xi[7]);
    c16 u3r = __hsub2(xr[3], xr[7]), u3i = __hsub2(xi[3], xi[7]);
    c16 o0r = __hadd2(u0r, u2r), o0i = __hadd2(u0i, u2i);
    c16 o2r = __hsub2(u0r, u2r), o2i = __hsub2(u0i, u2i);
    c16 o1r = __hsub2(u1r, u3i), o1i = __hadd2(u1i, u3r);
    c16 o3r = __hadd2(u1r, u3i), o3i = __hsub2(u1i, u3r);
    c16 w1r = __hmul2(C2, __hsub2(o1r, o1i)), w1i = __hmul2(C2, __hadd2(o1i, o1r));
    c16 w2r = __hneg2(o2i),                   w2i = o2r;
    c16 w3r = __hneg2(__hmul2(C2, __hadd2(o3r, o3i))), w3i = __hmul2(C2, __hsub2(o3r, o3i));
    xr[0] = __hadd2(e0r, o0r); xi[0] = __hadd2(e0i, o0i);
    xr[4] = __hsub2(e0r, o0r); xi[4] = __hsub2(e0i, o0i);
    xr[1] = __hadd2(e1r, w1r); xi[1] = __hadd2(e1i, w1i);
    xr[5] = __hsub2(e1r, w1r); xi[5] = __hsub2(e1i, w1i);
    xr[2] = __hadd2(e2r, w2r); xi[2] = __hadd2(e2i, w2i);
    xr[6] = __hsub2(e2r, w2r); xi[6] = __hsub2(e2i, w2i);
    xr[3] = __hadd2(e3r, w3r); xi[3] = __hadd2(e3i, w3i);
    xr[7] = __hsub2(e3r, w3r); xi[7] = __hsub2(e3i, w3i);
}

// comb16 inverse on 16 register words (all butterflies across words)
__device__ __forceinline__ void hcomb16s_inv(c16* re, c16* im,
                                             const c16* wrT, const c16* wiT) {
#pragma unroll
    for (int a = 0; a < 4; a++) hbfly4s_inv(re + 4 * a, im + 4 * a);
#pragma unroll
    for (int j = 0; j < 4; j++) {
        c16 yr[4], yi[4];
#pragma unroll
        for (int k = 0; k < 4; k++) { yr[k] = re[j + 4 * k]; yi[k] = im[j + 4 * k]; }
        if (j > 0) {
#pragma unroll
            for (int k = 1; k < 4; k++) hcmuls(yr[k], yi[k], wrT[8 * j * k], wiT[8 * j * k]);
        }
        hbfly4s_inv(yr, yi);
#pragma unroll
        for (int k = 0; k < 4; k++) { re[j + 4 * k] = yr[k]; im[j + 4 * k] = yi[k]; }
    }
}

// ---------------- stage A: i_hat = FFT2(image), s0 (fp32) --------------------
__global__ __launch_bounds__(NT, 1) void kA(const float* __restrict__ img) {
    extern __shared__ float2 sc[];
    __shared__ float s_twr[128], s_twi[128];
    __shared__ float red[32];
    int b = blockIdx.x;
    int tid = threadIdx.x;
    INIT_TWIDDLES();

    float local = 0.f;
    for (int idx = tid; idx < 16384; idx += NT) {
        float v = img[b * 16384 + idx];
        int r = idx >> 7, c = idx & 127;
        sc[r * NPAD + c] = make_float2(v, 0.f);
        local += v;
    }
    float s = block_sum<NT>(local, red);
    if (tid == 0) g_s0[b] = s * (1.f / 16384.f);
    __syncthreads();

    float2 tw6[6];
    LOAD_TW6(tw6, s_twr, s_twi);

    r8_stage<NT, false, 0>(sc, s_twr, s_twi);
    comb_stage<NT, false, 0>(sc, tw6);
    r8_stage<NT, false, 1>(sc, s_twr, s_twi);
    comb_stage<NT, false, 1>(sc, tw6);

    for (int idx = tid; idx < 16384; idx += NT) {
        int r = idx >> 7, c = idx & 127;
        g_ihat[b * 16384 + idx] = sc[r * NPAD + c];
    }
}

// ---------------- stage B: u1 = |ifft2(i_hat*psi)|, s1 partial, u1_hat -------
__global__ __launch_bounds__(NT, 2) void kB() {
    extern __shared__ __half2 shb[];
    __shared__ float s_twr[128], s_twi[128];
    __shared__ float red[32];
    int bi = blockIdx.x;              // b*16 + j1*4 + l1
    int b  = bi >> 4;
    int j1 = (bi >> 2) & 3;
    int tid = threadIdx.x;
    INIT_TWIDDLES();
    __syncthreads();

    float2 tw6[6];
    LOAD_TW6(tw6, s_twr, s_twi);

    const float2* src = g_ihat + (size_t)b * 16384;
    const float*  psi1 = g_psi + (((size_t)(bi & 15)) << 14);

    hpass_load_inv0_f32<NT>(shb, src, psi1, tw6);
    hr8_stage<NT, true, 0>(shb, s_twr, s_twi);
    hcomb_stage<NT, true, 1>(shb, tw6);
    float local = hpass_inv1_r8_mag<NT, true>(shb, s_twr, s_twi);
    float s = block_sum<NT>(local, red);
    if (tid == 0) g_s1part[bi] = s;
    __syncthreads();

    if (j1 < 3) {
        hr8_stage<NT, false, 0>(shb, s_twr, s_twi);
        hcomb_stage<NT, false, 0>(shb, tw6);
        hr8_stage<NT, false, 1>(shb, s_twr, s_twi);
        hpass_fwd1_store<NT>(shb, g_u1hat + (size_t)bi * 16384, tw6);
    }
}

// ---------------- stage C: half2-SoA pair-packed inverse + |.| ---------------
// planes: re/im, word [c][rpair] = component of rows (2t, 2t+1) at column c.
__global__ __launch_bounds__(NT, 2) void kC() {
    extern __shared__ c16 sm2[];
    c16* sre = sm2;
    c16* sim = sm2 + 128 * ST1;
    __shared__ c16 s_wr[128], s_wi[128];   // broadcast inverse twiddles (c,c),(s,s)
    __shared__ c16 s_c4r[64], s_c4i[64];   // C4 pair twiddles [j0*8+k]
    __shared__ c16 s_c3r[8], s_c3i[8];     // C3 stage2 pair twiddles [b*4+k]
    __shared__ float red[32];
    int bi = blockIdx.x;              // b*96 + pair*16 + l1*4 + l2
    int b    = bi / 96;
    int r96  = bi % 96;
    int pair = r96 >> 4;
    int l1   = (r96 >> 2) & 3;
    int l2   = r96 & 3;
    const int J1[6] = {0, 0, 0, 1, 1, 2};
    const int J2[6] = {1, 2, 3, 2, 3, 3};
    int j1 = J1[pair], j2 = J2[pair];
    int tid = threadIdx.x;

    if (tid < 128) {
        float sv, cv;
        __sincosf(2.f * PI_F * (float)tid / 128.f, &sv, &cv);   // inverse: e^{+i a}
        s_wr[tid] = __floats2half2_rn(cv, cv);
        s_wi[tid] = __floats2half2_rn(sv, sv);
    }
    if (tid < 64) {
        int J0 = tid >> 3, K = tid & 7;
        float a0 = 2.f * PI_F * (float)(2 * J0 * K) / 128.f;
        float a1 = 2.f * PI_F * (float)((2 * J0 + 1) * K) / 128.f;
        float s0v, c0v, s1v, c1v;
        __sincosf(a0, &s0v, &c0v);
        __sincosf(a1, &s1v, &c1v);
        s_c4r[tid] = __floats2half2_rn(c0v, c1v);
        s_c4i[tid] = __floats2half2_rn(s0v, s1v);
    }
    if (tid < 8) {
        int B = tid >> 2, K = tid & 3;
        float a0 = PI_F * (float)(2 * B * K) / 8.f;
        float a1 = PI_F * (float)((2 * B + 1) * K) / 8.f;
        float s0v, c0v, s1v, c1v;
        __sincosf(a0, &s0v, &c0v);
        __sincosf(a1, &s1v, &c1v);
        s_c3r[tid] = __floats2half2_rn(c0v, c1v);
        s_c3i[tid] = __floats2half2_rn(s0v, s1v);
    }
    __syncthreads();

    const c16* src = g_u1hat + (((size_t)b * 16 + j1 * 4 + l1) << 14);
    int f = j2 * 4 + l2;

    // ---- C1: gmem 2 rows -> SoA pack * psi-pair -> comb16 inv along c ------
    {
        int t = tid & 63, g = tid >> 6;
        const uint4* sA = reinterpret_cast<const uint4*>(src + (2 * t) * 128 + 16 * g);
        const uint4* sB = reinterpret_cast<const uint4*>(src + (2 * t + 1) * 128 + 16 * g);
        const uint4* pP = reinterpret_cast<const uint4*>(g_psihp + (((size_t)f * 8 + g) * 64 + t) * 16);
        uint4 a4[4] = {sA[0], sA[1], sA[2], sA[3]};
        uint4 b4[4] = {sB[0], sB[1], sB[2], sB[3]};
        uint4 p4[4] = {pP[0], pP[1], pP[2], pP[3]};
        const c16* ah = reinterpret_cast<const c16*>(a4);
        const c16* bh = reinterpret_cast<const c16*>(b4);
        const c16* ph = reinterpret_cast<const c16*>(p4);
        c16 re[16], im[16];
#pragma unroll
        for (int i = 0; i < 16; i++) {
            c16 va = ah[i], vb = bh[i], pw = ph[i];
            re[i] = __hmul2(__lows2half2(va, vb), pw);
            im[i] = __hmul2(__highs2half2(va, vb), pw);
        }
        hcomb16s_inv(re, im, s_wr, s_wi);
        int cb = 16 * g;
#pragma unroll
        for (int i = 0; i < 16; i++) {
            sre[(cb + i) * ST1 + t] = re[i];
            sim[(cb + i) * ST1 + t] = im[i];
        }
    }
    __syncthreads();

    // ---- C2: r8 inverse along c ---------------------------------------------
    {
        int j = tid >> 5, lane = tid & 31;
        c16 wr_[8], wi_[8];
#pragma unroll
        for (int k = 1; k < 8; k++) { wr_[k] = s_wr[j * k]; wi_[k] = s_wi[j * k]; }
#pragma unroll
        for (int it = 0; it < 2; it++) {
            int t = lane + 32 * it;
            c16 xr[8], xi[8];
#pragma unroll
            for (int k = 0; k < 8; k++) {
                int ad = (j + 16 * k) * ST1 + t;
                xr[k] = sre[ad]; xi[k] = sim[ad];
            }
#pragma unroll
            for (int k = 1; k < 8; k++) hcmuls(xr[k], xi[k], wr_[k], wi_[k]);
            hbfly8s_inv(xr, xi);
#pragma unroll
            for (int k = 0; k < 8; k++) {
                int ad = (j + 16 * k) * ST1 + t;
                sre[ad] = xr[k]; sim[ad] = xi[k];
            }
        }
    }
    __syncthreads();

    // ---- C3: comb16 inverse along r (packed dim; PRMT trick for stride-1) ---
    {
        const c16 PM = __floats2half2_rn(1.f, -1.f);
        const c16 MP = __floats2half2_rn(-1.f, 1.f);
#pragma unroll
        for (int it = 0; it < 2; it++) {
            int idx = tid + it * NT;
            int c = idx & 127, m = idx >> 7;
            int base = c * ST1 + 8 * m;
            c16 wr_[8], wi_[8];
#pragma unroll
            for (int i = 0; i < 8; i++) { wr_[i] = sre[base + i]; wi_[i] = sim[base + i]; }
            // stage1: stride-1 inverse bfly4 across word pairs (lane-mixing)
#pragma unroll
            for (int a = 0; a < 4; a++) {
                c16 ur = __hadd2(wr_[2 * a], wr_[2 * a + 1]);
                c16 vr = __hsub2(wr_[2 * a], wr_[2 * a + 1]);
                c16 ui = __hadd2(wi_[2 * a], wi_[2 * a + 1]);
                c16 vi = __hsub2(wi_[2 * a], wi_[2 * a + 1]);
                c16 P  = __lows2half2(ur, vr);   // (t0r, t1r)
                c16 Q  = __highs2half2(ur, vi);  // (t2r, t3i)
                c16 Pi = __lows2half2(ui, vi);   // (t0i, t1i)
                c16 Qi = __highs2half2(ui, vr);  // (t2i, t3r)
                wr_[2 * a]     = __hfma2(Q, PM, P);
                wr_[2 * a + 1] = __hfma2(Q, MP, P);
                wi_[2 * a]     = __hadd2(Pi, Qi);
                wi_[2 * a + 1] = __hsub2(Pi, Qi);
            }
            // stage2: mid (stride-4) — word-native with pair twiddles
#pragma unroll
            for (int bb = 0; bb < 2; bb++) {
                c16 yr[4], yi[4];
#pragma unroll
                for (int k = 0; k < 4; k++) { yr[k] = wr_[bb + 2 * k]; yi[k] = wi_[bb + 2 * k]; }
#pragma unroll
                for (int k = 1; k < 4; k++) hcmuls(yr[k], yi[k], s_c3r[bb * 4 + k], s_c3i[bb * 4 + k]);
                hbfly4s_inv(yr, yi);
#pragma unroll
                for (int k = 0; k < 4; k++) { wr_[bb + 2 * k] = yr[k]; wi_[bb + 2 * k] = yi[k]; }
            }
#pragma unroll
            for (int i = 0; i < 8; i++) { sre[base + i] = wr_[i]; sim[base + i] = wi_[i]; }
        }
    }
    __syncthreads();

    // ---- C4: r8 inverse along r + |.| (word = tap k of j-pair 2j0,2j0+1) ----
    float local = 0.f;
    {
        int j0 = tid >> 6, lane = tid & 63;
        c16 wr_[8], wi_[8];
#pragma unroll
        for (int k = 1; k < 8; k++) { wr_[k] = s_c4r[j0 * 8 + k]; wi_[k] = s_c4i[j0 * 8 + k]; }
#pragma unroll
        for (int it = 0; it < 2; it++) {
            int c = lane + 64 * it;
            c16 xr[8], xi[8];
#pragma unroll
            for (int k = 0; k < 8; k++) {
                int ad = c * ST1 + j0 + 8 * k;
                xr[k] = sre[ad]; xi[k] = sim[ad];
            }
#pragma unroll
            for (int k = 1; k < 8; k++) hcmuls(xr[k], xi[k], wr_[k], wi_[k]);
            hbfly8s_inv(xr, xi);
#pragma unroll
            for (int k = 0; k < 8; k++) {
                c16 m2 = __hfma2(xr[k], xr[k], __hmul2(xi[k], xi[k]));
                float2 fm = __half22float2(m2);
                local += sqrtf(fm.x) + sqrtf(fm.y);
            }
        }
    }
    float s = block_sum<NT>(local, red);
    if (tid == 0) g_s2part[bi] = s;
}

// ---------------- stage D: deterministic reduce + MLP ------------------------
__global__ void kD(const float* __restrict__ fc1w, const float* __restrict__ fc1b,
                   const float* __restrict__ fc2w, const float* __restrict__ fc2b,
                   float* __restrict__ out) {
    int b = threadIdx.x;
    if (b >= 64) return;
    float s[11];
    s[0] = g_s0[b];
    for (int j = 0; j < 4; j++) {
        float acc = 0.f;
        for (int l = 0; l < 4; l++) acc += g_s1part[b * 16 + j * 4 + l];
        s[1 + j] = acc * (1.f / (4.f * 16384.f));
    }
    for (int p = 0; p < 6; p++) {
        float acc = 0.f;
        for (int kk = 0; kk < 16; kk++) acc += g_s2part[b * 96 + p * 16 + kk];
        s[5 + p] = acc * (1.f / (16.f * 16384.f));
    }
    float h[4];
    for (int i = 0; i < 4; i++) {
        float a = fc1b[i];
        for (int t = 0; t < 11; t++) a += fc1w[i * 11 + t] * s[t];
        h[i] = fmaxf(a, 0.f);
    }
    for (int kk = 0; kk < 10; kk++) {
        float a = fc2b[kk];
        for (int i = 0; i < 4; i++) a += fc2w[kk * 4 + i] * h[i];
        out[b * 10 + kk] = 1.f / (1.f + expf(-a));
    }
}

// ---------------- launch -----------------------------------------------------
extern "C" void kernel_launch(void* const* d_in, const int* in_sizes, int n_in,
                              void* d_out, int out_size) {
    const float* img  = (const float*)d_in[0];
    const float* fc1w = (const float*)d_in[1];
    const float* fc1b = (const float*)d_in[2];
    const float* fc2w = (const float*)d_in[3];
    const float* fc2b = (const float*)d_in[4];
    float* out = (float*)d_out;

    const size_t smemA = 128 * NPAD * sizeof(float2);    // 132096 B
    const size_t smemB = 128 * SPAD * sizeof(__half2);   // 66048 B (2 CTAs/SM)
    const size_t smemC = 2 * 128 * ST1 * sizeof(__half2); // 66560 B (2 CTAs/SM)
    cudaFuncSetAttribute(kA, cudaFuncAttributeMaxDynamicSharedMemorySize, (int)smemA);
    cudaFuncSetAttribute(kB, cudaFuncAttributeMaxDynamicSharedMemorySize, (int)smemB);
    cudaFuncSetAttribute(kC, cudaFuncAttributeMaxDynamicSharedMemorySize, (int)smemC);

    init_psi_kernel<<<256, 1024>>>();
    kA<<<64, NT, smemA>>>(img);
    kB<<<1024, NT, smemB>>>();
    kC<<<6144, NT, smemC>>>();
    kD<<<1, 64>>>(fc1w, fc1b, fc2w, fc2b, out);
}